// round 1
// baseline (speedup 1.0000x reference)
#include <cuda_runtime.h>
#include <math.h>

#define BB 2
#define LL 1024
#define HH 512
#define DIM 1024
#define DI2 2048
#define NS 8
#define KC 4
#define RR 32
#define NLAYERS 4
#define VMX 300
#define NFEAT 4
#define MM (BB*LL)          /* 2048 rows */
#define SPW 48              /* R + 2N */
#define EPS 1e-5f

// -------------------- scratch (device globals; no allocation) --------------------
__device__ float g_h   [MM*HH];     // residual stream
__device__ float g_hn  [MM*HH];     // rmsnorm output
__device__ float g_proj[MM*DI2];    // in_proj output (hs_pre | gate)
__device__ float g_hs  [MM*DIM];    // conv+silu output
__device__ float g_sp  [MM*SPW];    // x_proj output
__device__ float g_dt  [MM*DIM];    // softplus(dt)
__device__ float g_y   [MM*DIM];    // scan output (gated)

// -------------------- embedding --------------------
__global__ void embed_kernel(const int* __restrict__ x, const float* __restrict__ emb) {
    int m = blockIdx.x;
    int t = threadIdx.x;       // 0..HH-1
    float s = 0.f;
#pragma unroll
    for (int i = 0; i < NFEAT; i++) {
        int v = x[m*NFEAT + i];
        s += emb[((size_t)i*VMX + v)*HH + t];
    }
    g_h[(size_t)m*HH + t] = s;
}

// -------------------- rmsnorm: g_hn = rmsnorm(g_h) * w --------------------
__global__ void rmsnorm_kernel(const float* __restrict__ w) {
    int m = blockIdx.x;
    int tid = threadIdx.x;     // 256 threads
    const float* row = g_h + (size_t)m*HH;
    float s = 0.f;
    for (int i = tid; i < HH; i += 256) { float v = row[i]; s += v*v; }
    __shared__ float red[256];
    red[tid] = s; __syncthreads();
    for (int st = 128; st > 0; st >>= 1) {
        if (tid < st) red[tid] += red[tid + st];
        __syncthreads();
    }
    float r = rsqrtf(red[0] * (1.f/HH) + EPS);
    for (int i = tid; i < HH; i += 256)
        g_hn[(size_t)m*HH + i] = row[i] * r * w[i];
}

// -------------------- generic tiled GEMM: C = A * B^T (+epilogue) --------------------
// A: [M, K] row stride lda ; B: [N, K] row stride ldb ; C: [M, N] row stride ldc
// mode 0: store ; 1: +bias then softplus ; 2: +resid (in-place residual) ; 3: +bias
#define TBM 64
#define TBN 64
#define TBK 16
__global__ __launch_bounds__(256)
void gemm_kernel(const float* __restrict__ A, const float* __restrict__ Bw,
                 const float* __restrict__ bias, const float* __restrict__ resid,
                 float* __restrict__ C,
                 int Mdim, int Ndim, int Kdim,
                 int lda, int ldb, int ldc, int mode)
{
    __shared__ float As[TBK][TBM + 4];
    __shared__ float Bs[TBK][TBN + 4];
    int tid = threadIdx.x;
    int tx = tid & 15;
    int ty = tid >> 4;
    int bm = blockIdx.y * TBM;
    int bn = blockIdx.x * TBN;

    float acc[4][4];
#pragma unroll
    for (int i = 0; i < 4; i++)
#pragma unroll
        for (int j = 0; j < 4; j++) acc[i][j] = 0.f;

    for (int k0 = 0; k0 < Kdim; k0 += TBK) {
#pragma unroll
        for (int i = 0; i < 4; i++) {
            int idx = tid + i*256;       // 0..1023
            int r = idx >> 4;            // 0..63
            int c = idx & 15;            // 0..15
            int gr = bm + r, gc = k0 + c;
            As[c][r] = (gr < Mdim && gc < Kdim) ? A[(size_t)gr*lda + gc] : 0.f;
            int gn = bn + r;
            Bs[c][r] = (gn < Ndim && gc < Kdim) ? Bw[(size_t)gn*ldb + gc] : 0.f;
        }
        __syncthreads();
#pragma unroll
        for (int kk = 0; kk < TBK; kk++) {
            float a0[4], b0[4];
#pragma unroll
            for (int i = 0; i < 4; i++) a0[i] = As[kk][ty*4 + i];
#pragma unroll
            for (int j = 0; j < 4; j++) b0[j] = Bs[kk][tx*4 + j];
#pragma unroll
            for (int i = 0; i < 4; i++)
#pragma unroll
                for (int j = 0; j < 4; j++) acc[i][j] += a0[i] * b0[j];
        }
        __syncthreads();
    }

#pragma unroll
    for (int i = 0; i < 4; i++) {
        int r = bm + ty*4 + i;
        if (r >= Mdim) continue;
#pragma unroll
        for (int j = 0; j < 4; j++) {
            int col = bn + tx*4 + j;
            if (col >= Ndim) continue;
            float v = acc[i][j];
            if (mode == 1) {
                v += bias[col];
                v = (v > 20.f) ? v : log1pf(expf(v));
            } else if (mode == 2) {
                v += resid[(size_t)r*ldc + col];
            } else if (mode == 3) {
                v += bias[col];
            }
            C[(size_t)r*ldc + col] = v;
        }
    }
}

// -------------------- causal depthwise conv (K=4) + silu --------------------
__global__ void conv_silu_kernel(const float* __restrict__ cw, const float* __restrict__ cb) {
    int m = blockIdx.x;                       // 0..MM-1
    int d = blockIdx.y * 256 + threadIdx.x;   // 0..DIM-1
    int b = m / LL, l = m % LL;
    float c = cb[d];
#pragma unroll
    for (int k = 0; k < KC; k++) {
        int li = l - (KC - 1) + k;
        if (li >= 0)
            c += g_proj[((size_t)(b*LL + li))*DI2 + d] * cw[d*KC + k];
    }
    // silu
    float s = c / (1.f + __expf(-c));
    g_hs[(size_t)m*DIM + d] = s;
}

// -------------------- selective scan --------------------
// one thread per (b, d, n); groups of 8 lanes reduce over n via shfl
__global__ void scan_kernel(const float* __restrict__ A_log_l,
                            const float* __restrict__ D_l) {
    int t = blockIdx.x * blockDim.x + threadIdx.x;  // 0..16383
    int n  = t & 7;
    int gd = t >> 3;          // 0..2047
    int b  = gd >> 10;
    int d  = gd & 1023;

    float A  = -__expf(A_log_l[d*NS + n]);
    float Dv = D_l[d];
    float state = 0.f;

    for (int l = 0; l < LL; l++) {
        int m = b*LL + l;
        float dtv = g_dt[(size_t)m*DIM + d];
        float hsv = g_hs[(size_t)m*DIM + d];
        float Bv  = g_sp[(size_t)m*SPW + RR + n];
        float Cv  = g_sp[(size_t)m*SPW + RR + NS + n];
        float dA  = __expf(dtv * A);
        state = dA * state + (dtv * hsv) * Bv;
        float yv = state * Cv;
        yv += __shfl_xor_sync(0xffffffffu, yv, 1);
        yv += __shfl_xor_sync(0xffffffffu, yv, 2);
        yv += __shfl_xor_sync(0xffffffffu, yv, 4);
        if (n == 0) {
            float g  = g_proj[(size_t)m*DI2 + DIM + d];
            float sg = g / (1.f + __expf(-g));
            g_y[(size_t)m*DIM + d] = (yv + hsv * Dv) * sg;
        }
    }
}

// -------------------- launcher --------------------
extern "C" void kernel_launch(void* const* d_in, const int* in_sizes, int n_in,
                              void* d_out, int out_size)
{
    const int*   x         = (const int*)  d_in[0];
    const float* emb       = (const float*)d_in[1];
    const float* in_proj_w = (const float*)d_in[2];
    const float* conv_w    = (const float*)d_in[3];
    const float* conv_b    = (const float*)d_in[4];
    const float* x_proj_w  = (const float*)d_in[5];
    const float* dt_proj_w = (const float*)d_in[6];
    const float* dt_proj_b = (const float*)d_in[7];
    const float* A_log     = (const float*)d_in[8];
    const float* D_ssm     = (const float*)d_in[9];
    const float* out_proj_w= (const float*)d_in[10];
    const float* norm_w    = (const float*)d_in[11];
    const float* norm_f_w  = (const float*)d_in[12];
    const float* head_w    = (const float*)d_in[13];
    const float* head_b    = (const float*)d_in[14];
    float* out = (float*)d_out;

    float *p_hn, *p_proj, *p_hs, *p_sp, *p_dt, *p_y, *p_h;
    cudaGetSymbolAddress((void**)&p_h,    g_h);
    cudaGetSymbolAddress((void**)&p_hn,   g_hn);
    cudaGetSymbolAddress((void**)&p_proj, g_proj);
    cudaGetSymbolAddress((void**)&p_hs,   g_hs);
    cudaGetSymbolAddress((void**)&p_sp,   g_sp);
    cudaGetSymbolAddress((void**)&p_dt,   g_dt);
    cudaGetSymbolAddress((void**)&p_y,    g_y);

    embed_kernel<<<MM, HH>>>(x, emb);

    for (int l = 0; l < NLAYERS; l++) {
        rmsnorm_kernel<<<MM, 256>>>(norm_w + l*HH);

        // in_proj: [MM,512] x [2048,512]^T -> g_proj [MM,2048]
        gemm_kernel<<<dim3(DI2/TBN, MM/TBM), 256>>>(
            p_hn, in_proj_w + (size_t)l*DI2*HH, nullptr, nullptr, p_proj,
            MM, DI2, HH, HH, HH, DI2, 0);

        conv_silu_kernel<<<dim3(MM, DIM/256), 256>>>(
            conv_w + (size_t)l*DIM*KC, conv_b + l*DIM);

        // x_proj: [MM,1024] x [48,1024]^T -> g_sp [MM,48]
        gemm_kernel<<<dim3(1, MM/TBM), 256>>>(
            p_hs, x_proj_w + (size_t)l*SPW*DIM, nullptr, nullptr, p_sp,
            MM, SPW, DIM, DIM, DIM, SPW, 0);

        // dt_proj: [MM,32 (stride 48)] x [1024,32]^T + bias, softplus -> g_dt
        gemm_kernel<<<dim3(DIM/TBN, MM/TBM), 256>>>(
            p_sp, dt_proj_w + (size_t)l*DIM*RR, dt_proj_b + l*DIM, nullptr, p_dt,
            MM, DIM, RR, SPW, RR, DIM, 1);

        scan_kernel<<<(BB*DIM*NS)/256, 256>>>(
            A_log + (size_t)l*DIM*NS, D_ssm + l*DIM);

        // out_proj + residual: g_h += g_y x [512,1024]^T
        gemm_kernel<<<dim3(HH/TBN, MM/TBM), 256>>>(
            p_y, out_proj_w + (size_t)l*HH*DIM, nullptr, p_h, p_h,
            MM, HH, DIM, DIM, DIM, HH, 2);
    }

    rmsnorm_kernel<<<MM, 256>>>(norm_f_w);

    // head: [MM,512] x [300,512]^T + bias -> out [MM,300]
    gemm_kernel<<<dim3((VMX + TBN - 1)/TBN, MM/TBM), 256>>>(
        p_hn, head_w, head_b, nullptr, out,
        MM, VMX, HH, HH, HH, VMX, 3);
}

// round 2
// speedup vs baseline: 1.0052x; 1.0052x over previous
#include <cuda_runtime.h>
#include <math.h>

#define BB 2
#define LL 1024
#define HH 512
#define DIM 1024
#define DI2 2048
#define NS 8
#define KC 4
#define RR 32
#define NLAYERS 4
#define VMX 300
#define NFEAT 4
#define MM (BB*LL)          /* 2048 rows */
#define SPW 48              /* R + 2N */
#define EPS 1e-5f

// -------------------- scratch (device globals; no allocation) --------------------
__device__ float g_h   [MM*HH];     // residual stream
__device__ float g_hn  [MM*HH];     // rmsnorm output
__device__ float g_proj[MM*DI2];    // in_proj output (hs_pre | gate)
__device__ float g_hs  [MM*DIM];    // conv+silu output
__device__ float g_sp  [MM*SPW];    // x_proj output
__device__ float g_dt  [MM*DIM];    // softplus(dt)
__device__ float g_y   [MM*DIM];    // scan output (gated)

// -------------------- embedding --------------------
__global__ void embed_kernel(const int* __restrict__ x, const float* __restrict__ emb) {
    int m = blockIdx.x;
    int t = threadIdx.x;       // 0..HH-1
    float s = 0.f;
#pragma unroll
    for (int i = 0; i < NFEAT; i++) {
        int v = x[m*NFEAT + i];
        s += emb[((size_t)i*VMX + v)*HH + t];
    }
    g_h[(size_t)m*HH + t] = s;
}

// -------------------- rmsnorm: g_hn = rmsnorm(g_h) * w --------------------
__global__ void rmsnorm_kernel(const float* __restrict__ w) {
    int m = blockIdx.x;
    int tid = threadIdx.x;     // 256 threads
    const float* row = g_h + (size_t)m*HH;
    float s = 0.f;
    for (int i = tid; i < HH; i += 256) { float v = row[i]; s += v*v; }
    __shared__ float red[256];
    red[tid] = s; __syncthreads();
    for (int st = 128; st > 0; st >>= 1) {
        if (tid < st) red[tid] += red[tid + st];
        __syncthreads();
    }
    float r = rsqrtf(red[0] * (1.f/HH) + EPS);
    for (int i = tid; i < HH; i += 256)
        g_hn[(size_t)m*HH + i] = row[i] * r * w[i];
}

// -------------------- SGEMM: C = A * B^T (+epilogue) --------------------
// A: [M, K] row stride lda ; B: [N, K] row stride ldb ; C: [M, N] row stride ldc
// 128x128 tile, BK=8, 256 threads, 8x8 per thread (2x2 quadrants of 4x4).
// Requires: M % 128 == 0, K % 8 == 0, lda/ldb multiples of 4, bases 16B-aligned.
// mode 0: store ; 1: +bias then softplus ; 2: +resid (residual accumulate) ; 3: +bias
#define BM 128
#define BN 128
#define BK 8
#define LDS_PAD 132   /* floats per SMEM row; 132*4=528 bytes, 16B-aligned, conflict-free */

__global__ __launch_bounds__(256, 2)
void sgemm_kernel(const float* __restrict__ A, const float* __restrict__ Bw,
                  const float* __restrict__ bias, const float* __restrict__ resid,
                  float* __restrict__ C,
                  int Mdim, int Ndim, int Kdim,
                  int lda, int ldb, int ldc, int mode)
{
    __shared__ float As[2][BK][LDS_PAD];
    __shared__ float Bs[2][BK][LDS_PAD];

    const int tid  = threadIdx.x;
    const int row  = tid >> 1;          // 0..127 (tile row for loads)
    const int kseg = (tid & 1) * 4;     // 0 or 4 (k offset for float4 load)
    const int tx   = tid & 15;          // n-dir thread coord
    const int ty   = tid >> 4;          // m-dir thread coord
    const int bm   = blockIdx.y * BM;
    const int bn   = blockIdx.x * BN;

    const bool aRowOk = (bm + row) < Mdim;   // always true for our shapes
    const bool bRowOk = (bn + row) < Ndim;

    const float* aPtr = A  + (size_t)(bm + row) * lda + kseg;
    const float* bPtr = Bw + (size_t)(bn + row) * ldb + kseg;

    float acc[8][8];
#pragma unroll
    for (int i = 0; i < 8; i++)
#pragma unroll
        for (int j = 0; j < 8; j++) acc[i][j] = 0.f;

    const int nIt = Kdim / BK;

    // prologue: load tile 0
    float4 aReg = aRowOk ? *reinterpret_cast<const float4*>(aPtr)
                         : make_float4(0.f,0.f,0.f,0.f);
    float4 bReg = bRowOk ? *reinterpret_cast<const float4*>(bPtr)
                         : make_float4(0.f,0.f,0.f,0.f);
    {
        As[0][kseg+0][row] = aReg.x; As[0][kseg+1][row] = aReg.y;
        As[0][kseg+2][row] = aReg.z; As[0][kseg+3][row] = aReg.w;
        Bs[0][kseg+0][row] = bReg.x; Bs[0][kseg+1][row] = bReg.y;
        Bs[0][kseg+2][row] = bReg.z; Bs[0][kseg+3][row] = bReg.w;
    }
    __syncthreads();

    int buf = 0;
    for (int it = 0; it < nIt; it++) {
        // prefetch next K-slab into registers (latency hidden by FFMAs below)
        if (it + 1 < nIt) {
            const float* ap = aPtr + (size_t)(it + 1) * BK;
            const float* bp = bPtr + (size_t)(it + 1) * BK;
            aReg = aRowOk ? *reinterpret_cast<const float4*>(ap)
                          : make_float4(0.f,0.f,0.f,0.f);
            bReg = bRowOk ? *reinterpret_cast<const float4*>(bp)
                          : make_float4(0.f,0.f,0.f,0.f);
        }

#pragma unroll
        for (int kk = 0; kk < BK; kk++) {
            float4 a0 = *reinterpret_cast<const float4*>(&As[buf][kk][ty*4]);
            float4 a1 = *reinterpret_cast<const float4*>(&As[buf][kk][64 + ty*4]);
            float4 b0 = *reinterpret_cast<const float4*>(&Bs[buf][kk][tx*4]);
            float4 b1 = *reinterpret_cast<const float4*>(&Bs[buf][kk][64 + tx*4]);
            float av[8] = {a0.x,a0.y,a0.z,a0.w, a1.x,a1.y,a1.z,a1.w};
            float bv[8] = {b0.x,b0.y,b0.z,b0.w, b1.x,b1.y,b1.z,b1.w};
#pragma unroll
            for (int i = 0; i < 8; i++)
#pragma unroll
                for (int j = 0; j < 8; j++)
                    acc[i][j] += av[i] * bv[j];
        }

        if (it + 1 < nIt) {
            int nb = buf ^ 1;
            As[nb][kseg+0][row] = aReg.x; As[nb][kseg+1][row] = aReg.y;
            As[nb][kseg+2][row] = aReg.z; As[nb][kseg+3][row] = aReg.w;
            Bs[nb][kseg+0][row] = bReg.x; Bs[nb][kseg+1][row] = bReg.y;
            Bs[nb][kseg+2][row] = bReg.z; Bs[nb][kseg+3][row] = bReg.w;
            __syncthreads();
            buf = nb;
        }
    }

    // epilogue
#pragma unroll
    for (int i = 0; i < 8; i++) {
        int r = bm + ((i < 4) ? (ty*4 + i) : (64 + ty*4 + i - 4));
        if (r >= Mdim) continue;
#pragma unroll
        for (int j = 0; j < 8; j++) {
            int col = bn + ((j < 4) ? (tx*4 + j) : (64 + tx*4 + j - 4));
            if (col >= Ndim) continue;
            float v = acc[i][j];
            if (mode == 1) {
                v += bias[col];
                v = (v > 20.f) ? v : log1pf(expf(v));
            } else if (mode == 2) {
                v += resid[(size_t)r*ldc + col];
            } else if (mode == 3) {
                v += bias[col];
            }
            C[(size_t)r*ldc + col] = v;
        }
    }
}

// -------------------- causal depthwise conv (K=4) + silu --------------------
__global__ void conv_silu_kernel(const float* __restrict__ cw, const float* __restrict__ cb) {
    int m = blockIdx.x;                       // 0..MM-1
    int d = blockIdx.y * 256 + threadIdx.x;   // 0..DIM-1
    int b = m / LL, l = m % LL;
    float c = cb[d];
#pragma unroll
    for (int k = 0; k < KC; k++) {
        int li = l - (KC - 1) + k;
        if (li >= 0)
            c += g_proj[((size_t)(b*LL + li))*DI2 + d] * cw[d*KC + k];
    }
    float s = c / (1.f + __expf(-c));
    g_hs[(size_t)m*DIM + d] = s;
}

// -------------------- selective scan --------------------
// one thread per (b, d, n); groups of 8 lanes reduce over n via shfl
__global__ void scan_kernel(const float* __restrict__ A_log_l,
                            const float* __restrict__ D_l) {
    int t = blockIdx.x * blockDim.x + threadIdx.x;  // 0..16383
    int n  = t & 7;
    int gd = t >> 3;          // 0..2047
    int b  = gd >> 10;
    int d  = gd & 1023;

    float A  = -__expf(A_log_l[d*NS + n]);
    float Dv = D_l[d];
    float state = 0.f;

    for (int l = 0; l < LL; l++) {
        int m = b*LL + l;
        float dtv = g_dt[(size_t)m*DIM + d];
        float hsv = g_hs[(size_t)m*DIM + d];
        float Bv  = g_sp[(size_t)m*SPW + RR + n];
        float Cv  = g_sp[(size_t)m*SPW + RR + NS + n];
        float dA  = __expf(dtv * A);
        state = dA * state + (dtv * hsv) * Bv;
        float yv = state * Cv;
        yv += __shfl_xor_sync(0xffffffffu, yv, 1);
        yv += __shfl_xor_sync(0xffffffffu, yv, 2);
        yv += __shfl_xor_sync(0xffffffffu, yv, 4);
        if (n == 0) {
            float g  = g_proj[(size_t)m*DI2 + DIM + d];
            float sg = g / (1.f + __expf(-g));
            g_y[(size_t)m*DIM + d] = (yv + hsv * Dv) * sg;
        }
    }
}

// -------------------- launcher --------------------
extern "C" void kernel_launch(void* const* d_in, const int* in_sizes, int n_in,
                              void* d_out, int out_size)
{
    const int*   x         = (const int*)  d_in[0];
    const float* emb       = (const float*)d_in[1];
    const float* in_proj_w = (const float*)d_in[2];
    const float* conv_w    = (const float*)d_in[3];
    const float* conv_b    = (const float*)d_in[4];
    const float* x_proj_w  = (const float*)d_in[5];
    const float* dt_proj_w = (const float*)d_in[6];
    const float* dt_proj_b = (const float*)d_in[7];
    const float* A_log     = (const float*)d_in[8];
    const float* D_ssm     = (const float*)d_in[9];
    const float* out_proj_w= (const float*)d_in[10];
    const float* norm_w    = (const float*)d_in[11];
    const float* norm_f_w  = (const float*)d_in[12];
    const float* head_w    = (const float*)d_in[13];
    const float* head_b    = (const float*)d_in[14];
    float* out = (float*)d_out;

    float *p_hn, *p_proj, *p_hs, *p_sp, *p_dt, *p_y, *p_h;
    cudaGetSymbolAddress((void**)&p_h,    g_h);
    cudaGetSymbolAddress((void**)&p_hn,   g_hn);
    cudaGetSymbolAddress((void**)&p_proj, g_proj);
    cudaGetSymbolAddress((void**)&p_hs,   g_hs);
    cudaGetSymbolAddress((void**)&p_sp,   g_sp);
    cudaGetSymbolAddress((void**)&p_dt,   g_dt);
    cudaGetSymbolAddress((void**)&p_y,    g_y);

    embed_kernel<<<MM, HH>>>(x, emb);

    for (int l = 0; l < NLAYERS; l++) {
        rmsnorm_kernel<<<MM, 256>>>(norm_w + l*HH);

        // in_proj: [MM,512] x [2048,512]^T -> g_proj [MM,2048]
        sgemm_kernel<<<dim3(DI2/BN, MM/BM), 256>>>(
            p_hn, in_proj_w + (size_t)l*DI2*HH, nullptr, nullptr, p_proj,
            MM, DI2, HH, HH, HH, DI2, 0);

        conv_silu_kernel<<<dim3(MM, DIM/256), 256>>>(
            conv_w + (size_t)l*DIM*KC, conv_b + l*DIM);

        // x_proj: [MM,1024] x [48,1024]^T -> g_sp [MM,48]
        sgemm_kernel<<<dim3(1, MM/BM), 256>>>(
            p_hs, x_proj_w + (size_t)l*SPW*DIM, nullptr, nullptr, p_sp,
            MM, SPW, DIM, DIM, DIM, SPW, 0);

        // dt_proj: [MM,32 (stride 48)] x [1024,32]^T + bias, softplus -> g_dt
        sgemm_kernel<<<dim3(DIM/BN, MM/BM), 256>>>(
            p_sp, dt_proj_w + (size_t)l*DIM*RR, dt_proj_b + l*DIM, nullptr, p_dt,
            MM, DIM, RR, SPW, RR, DIM, 1);

        scan_kernel<<<(BB*DIM*NS)/256, 256>>>(
            A_log + (size_t)l*DIM*NS, D_ssm + l*DIM);

        // out_proj + residual: g_h += g_y x [512,1024]^T
        sgemm_kernel<<<dim3(HH/BN, MM/BM), 256>>>(
            p_y, out_proj_w + (size_t)l*HH*DIM, nullptr, p_h, p_h,
            MM, HH, DIM, DIM, DIM, HH, 2);
    }

    rmsnorm_kernel<<<MM, 256>>>(norm_f_w);

    // head: [MM,512] x [300,512]^T + bias -> out [MM,300]
    sgemm_kernel<<<dim3((VMX + BN - 1)/BN, MM/BM), 256>>>(
        p_hn, head_w, head_b, nullptr, out,
        MM, VMX, HH, HH, HH, VMX, 3);
}

// round 4
// speedup vs baseline: 3.3646x; 3.3471x over previous
#include <cuda_runtime.h>
#include <cuda_bf16.h>
#include <math.h>
#include <stdint.h>

#define BB 2
#define LL 1024
#define HH 512
#define DIM 1024
#define DI2 2048
#define NS 8
#define KC 4
#define RR 32
#define NLAYERS 4
#define VMX 300
#define NFEAT 4
#define MM (BB*LL)          /* 2048 rows */
#define SPW 48              /* R + 2N */
#define EPS 1e-5f

#define NCHUNK 8
#define CLEN (LL/NCHUNK)    /* 128 */
#define NLANES (BB*DIM*NS)  /* 16384 */

// -------------------- scratch (device globals; no allocation) --------------------
__device__ float g_h   [MM*HH];
__device__ float g_hn  [MM*HH];
__device__ float g_proj[MM*DI2];
__device__ float g_hs  [MM*DIM];
__device__ float g_sp  [MM*SPW];
__device__ float g_dt  [MM*DIM];
__device__ float g_y   [MM*DIM];
__device__ float g_sloc[NCHUNK*NLANES];
__device__ float g_prod[NCHUNK*NLANES];
__device__ float g_sst [NCHUNK*NLANES];

// ==================== mma.sync helpers (sm_80+ ISA, works on sm_100) ====================
__device__ __forceinline__ void ldsm4(uint32_t* r, uint32_t addr) {
    asm volatile("ldmatrix.sync.aligned.m8n8.x4.shared.b16 {%0,%1,%2,%3}, [%4];"
                 : "=r"(r[0]), "=r"(r[1]), "=r"(r[2]), "=r"(r[3]) : "r"(addr));
}
__device__ __forceinline__ void mma_bf16(float* d, const uint32_t* a, const uint32_t* b) {
    asm volatile(
        "mma.sync.aligned.m16n8k16.row.col.f32.bf16.bf16.f32 "
        "{%0,%1,%2,%3}, {%4,%5,%6,%7}, {%8,%9}, {%0,%1,%2,%3};"
        : "+f"(d[0]), "+f"(d[1]), "+f"(d[2]), "+f"(d[3])
        : "r"(a[0]), "r"(a[1]), "r"(a[2]), "r"(a[3]), "r"(b[0]), "r"(b[1]));
}
__device__ __forceinline__ uint32_t smem_u32(const void* p) {
    return (uint32_t)__cvta_generic_to_shared(p);
}

// ==================== tensor-core GEMM: C = A * B^T (+epilogue) ====================
// A: [M,K] f32 (lda), B: [N,K] f32 (ldb), C: [M,N] (ldc)
// CTA tile 128x128, K chunk 32. bf16 hi/lo split: 3 MMAs per product step.
// Requires: M%128==0, K%32==0, Ndim even, lda/ldb %4==0.
// mode 0: store ; 1: +bias softplus ; 2: +resid ; 3: +bias
#define SST 40                      /* SMEM row stride in bf16 elems (80 B) */
#define TILE_B (128*SST*2)          /* 10240 B per bf16 tile */
#define STAGE_B (4*TILE_B)          /* Ahi|Alo|Bhi|Blo = 40960 B */
#define GSMEM (2*STAGE_B)           /* 81920 B */

__device__ __forceinline__ void cvt_store16(const float* v, char* hiT, char* loT,
                                            int arow, int kb) {
    uint32_t hi[8], lo[8];
#pragma unroll
    for (int q = 0; q < 8; q++) {
        float f0 = v[2*q], f1 = v[2*q+1];
        __nv_bfloat16 h0 = __float2bfloat16_rn(f0);
        __nv_bfloat16 h1 = __float2bfloat16_rn(f1);
        __nv_bfloat16 l0 = __float2bfloat16_rn(f0 - __bfloat162float(h0));
        __nv_bfloat16 l1 = __float2bfloat16_rn(f1 - __bfloat162float(h1));
        hi[q] = ((uint32_t)__bfloat16_as_ushort(h1) << 16) | (uint32_t)__bfloat16_as_ushort(h0);
        lo[q] = ((uint32_t)__bfloat16_as_ushort(l1) << 16) | (uint32_t)__bfloat16_as_ushort(l0);
    }
    char* dh = hiT + arow*(SST*2) + kb*2;
    char* dl = loT + arow*(SST*2) + kb*2;
    *reinterpret_cast<uint4*>(dh)      = make_uint4(hi[0],hi[1],hi[2],hi[3]);
    *reinterpret_cast<uint4*>(dh + 16) = make_uint4(hi[4],hi[5],hi[6],hi[7]);
    *reinterpret_cast<uint4*>(dl)      = make_uint4(lo[0],lo[1],lo[2],lo[3]);
    *reinterpret_cast<uint4*>(dl + 16) = make_uint4(lo[4],lo[5],lo[6],lo[7]);
}

__global__ __launch_bounds__(256, 1)
void gemm_tc(const float* __restrict__ A, const float* __restrict__ Bw,
             const float* __restrict__ bias, const float* __restrict__ resid,
             float* __restrict__ C,
             int Mdim, int Ndim, int Kdim,
             int lda, int ldb, int ldc, int mode)
{
    extern __shared__ char sm[];
    const int tid  = threadIdx.x;
    const int lane = tid & 31;
    const int wid  = tid >> 5;
    const int warpM = wid & 3;       // 0..3
    const int warpN = wid >> 2;      // 0..1
    const int bm = blockIdx.y * 128;
    const int bn = blockIdx.x * 128;

    // loader coords: 2 threads per row, 16 f32 each
    const int arow = tid >> 1;
    const int kb   = (tid & 1) * 16;
    const float* aP = A + (size_t)(bm + arow) * lda + kb;
    const int brow = bn + arow;
    const float* bP = Bw + (size_t)brow * ldb + kb;
    const bool bOk = brow < Ndim;

    float acc[2][8][4];
#pragma unroll
    for (int i = 0; i < 2; i++)
#pragma unroll
        for (int j = 0; j < 8; j++)
#pragma unroll
            for (int q = 0; q < 4; q++) acc[i][j][q] = 0.f;

    const int nch = Kdim / 32;
    float aS[16], bS[16];

    // prologue: chunk 0 -> regs -> smem buf0
    {
#pragma unroll
        for (int q = 0; q < 4; q++) {
            float4 av = *reinterpret_cast<const float4*>(aP + q*4);
            aS[4*q+0]=av.x; aS[4*q+1]=av.y; aS[4*q+2]=av.z; aS[4*q+3]=av.w;
            float4 bv = bOk ? *reinterpret_cast<const float4*>(bP + q*4)
                            : make_float4(0.f,0.f,0.f,0.f);
            bS[4*q+0]=bv.x; bS[4*q+1]=bv.y; bS[4*q+2]=bv.z; bS[4*q+3]=bv.w;
        }
        char* st = sm;
        cvt_store16(aS, st,            st + TILE_B,   arow, kb);
        cvt_store16(bS, st + 2*TILE_B, st + 3*TILE_B, arow, kb);
    }
    __syncthreads();

    for (int ci = 0; ci < nch; ci++) {
        const int s = ci & 1;
        char* st = sm + s * STAGE_B;
        const uint32_t uAh = smem_u32(st);
        const uint32_t uAl = uAh + TILE_B;
        const uint32_t uBh = uAh + 2*TILE_B;
        const uint32_t uBl = uAh + 3*TILE_B;

        // prefetch next chunk into regs
        if (ci + 1 < nch) {
            const int k0 = (ci + 1) * 32;
#pragma unroll
            for (int q = 0; q < 4; q++) {
                float4 av = *reinterpret_cast<const float4*>(aP + k0 + q*4);
                aS[4*q+0]=av.x; aS[4*q+1]=av.y; aS[4*q+2]=av.z; aS[4*q+3]=av.w;
                float4 bv = bOk ? *reinterpret_cast<const float4*>(bP + k0 + q*4)
                                : make_float4(0.f,0.f,0.f,0.f);
                bS[4*q+0]=bv.x; bS[4*q+1]=bv.y; bS[4*q+2]=bv.z; bS[4*q+3]=bv.w;
            }
        }

        // compute: 2 k16 steps
#pragma unroll
        for (int ks = 0; ks < 2; ks++) {
            uint32_t afh[2][4], afl[2][4], bfh[8][2], bfl[8][2];
            const int kcA = ks*16 + (lane >> 4) * 8;          // bf16 col
            const int rA0 = warpM*32 + (lane & 15);
#pragma unroll
            for (int mi = 0; mi < 2; mi++) {
                uint32_t off = (uint32_t)(rA0 + mi*16) * (SST*2) + (uint32_t)kcA * 2;
                ldsm4(afh[mi], uAh + off);
                ldsm4(afl[mi], uAl + off);
            }
            const int rB0 = warpN*64 + (lane & 7) + ((lane >> 4) << 3);
            const int kcB = ks*16 + ((lane >> 3) & 1) * 8;
#pragma unroll
            for (int g = 0; g < 4; g++) {
                uint32_t off = (uint32_t)(rB0 + g*16) * (SST*2) + (uint32_t)kcB * 2;
                uint32_t t4[4];
                ldsm4(t4, uBh + off);
                bfh[2*g][0]=t4[0]; bfh[2*g][1]=t4[1]; bfh[2*g+1][0]=t4[2]; bfh[2*g+1][1]=t4[3];
                ldsm4(t4, uBl + off);
                bfl[2*g][0]=t4[0]; bfl[2*g][1]=t4[1]; bfl[2*g+1][0]=t4[2]; bfl[2*g+1][1]=t4[3];
            }
#pragma unroll
            for (int mi = 0; mi < 2; mi++)
#pragma unroll
                for (int g = 0; g < 8; g++) {
                    mma_bf16(acc[mi][g], afh[mi], bfh[g]);
                    mma_bf16(acc[mi][g], afh[mi], bfl[g]);
                    mma_bf16(acc[mi][g], afl[mi], bfh[g]);
                }
        }

        if (ci + 1 < nch) {
            char* stn = sm + ((ci + 1) & 1) * STAGE_B;
            cvt_store16(aS, stn,            stn + TILE_B,   arow, kb);
            cvt_store16(bS, stn + 2*TILE_B, stn + 3*TILE_B, arow, kb);
            __syncthreads();
        }
    }

    // epilogue: frag -> C
#pragma unroll
    for (int mi = 0; mi < 2; mi++) {
        const int row0 = bm + warpM*32 + mi*16 + (lane >> 2);
#pragma unroll
        for (int g = 0; g < 8; g++) {
            const int col = bn + warpN*64 + g*8 + (lane & 3)*2;
            if (col >= Ndim) continue;
#pragma unroll
            for (int h = 0; h < 2; h++) {
                const int r = row0 + h*8;
                float v0 = acc[mi][g][2*h+0];
                float v1 = acc[mi][g][2*h+1];
                if (mode == 1) {
                    v0 += bias[col]; v1 += bias[col+1];
                    v0 = (v0 > 20.f) ? v0 : log1pf(expf(v0));
                    v1 = (v1 > 20.f) ? v1 : log1pf(expf(v1));
                } else if (mode == 2) {
                    const float2 rr = *reinterpret_cast<const float2*>(resid + (size_t)r*ldc + col);
                    v0 += rr.x; v1 += rr.y;
                } else if (mode == 3) {
                    v0 += bias[col]; v1 += bias[col+1];
                }
                *reinterpret_cast<float2*>(C + (size_t)r*ldc + col) = make_float2(v0, v1);
            }
        }
    }
}

// -------------------- embedding --------------------
__global__ void embed_kernel(const int* __restrict__ x, const float* __restrict__ emb) {
    int m = blockIdx.x;
    int t = threadIdx.x;
    float s = 0.f;
#pragma unroll
    for (int i = 0; i < NFEAT; i++) {
        int v = x[m*NFEAT + i];
        s += emb[((size_t)i*VMX + v)*HH + t];
    }
    g_h[(size_t)m*HH + t] = s;
}

// -------------------- rmsnorm --------------------
__global__ void rmsnorm_kernel(const float* __restrict__ w) {
    int m = blockIdx.x;
    int tid = threadIdx.x;
    const float* row = g_h + (size_t)m*HH;
    float s = 0.f;
    for (int i = tid; i < HH; i += 256) { float v = row[i]; s += v*v; }
    __shared__ float red[256];
    red[tid] = s; __syncthreads();
    for (int st = 128; st > 0; st >>= 1) {
        if (tid < st) red[tid] += red[tid + st];
        __syncthreads();
    }
    float r = rsqrtf(red[0] * (1.f/HH) + EPS);
    for (int i = tid; i < HH; i += 256)
        g_hn[(size_t)m*HH + i] = row[i] * r * w[i];
}

// -------------------- causal depthwise conv (K=4) + silu --------------------
__global__ void conv_silu_kernel(const float* __restrict__ cw, const float* __restrict__ cb) {
    int m = blockIdx.x;
    int d = blockIdx.y * 256 + threadIdx.x;
    int b = m / LL, l = m % LL;
    float c = cb[d];
#pragma unroll
    for (int k = 0; k < KC; k++) {
        int li = l - (KC - 1) + k;
        if (li >= 0)
            c += g_proj[((size_t)(b*LL + li))*DI2 + d] * cw[d*KC + k];
    }
    float s = c / (1.f + __expf(-c));
    g_hs[(size_t)m*DIM + d] = s;
}

// -------------------- chunked selective scan --------------------
// lane t within 16384: n = t&7, d = (t>>3)&1023, b = (t>>13)&1
// pass1: per-chunk local scan with s0=0; record final state + dA product
__global__ void scan_part1(const float* __restrict__ A_log_l) {
    int t = blockIdx.x * blockDim.x + threadIdx.x;   // 0..131071
    int c = t >> 14;
    int u = t & (NLANES-1);
    int n = u & 7;
    int d = (u >> 3) & 1023;
    int b = (u >> 13) & 1;

    float A = -__expf(A_log_l[d*NS + n]);
    float s = 0.f, P = 1.f;
    int l0 = c * CLEN;
    for (int l = l0; l < l0 + CLEN; l++) {
        int m = b*LL + l;
        float dtv = g_dt[(size_t)m*DIM + d];
        float hsv = g_hs[(size_t)m*DIM + d];
        float Bv  = g_sp[(size_t)m*SPW + RR + n];
        float dA  = __expf(dtv * A);
        s = dA * s + (dtv * hsv) * Bv;
        P *= dA;
    }
    g_sloc[t] = s;
    g_prod[t] = P;
}

// pass2: serial combine over 8 chunks per lane
__global__ void scan_part2() {
    int u = blockIdx.x * blockDim.x + threadIdx.x;   // 0..16383
    float s = 0.f;
#pragma unroll
    for (int c = 0; c < NCHUNK; c++) {
        g_sst[c*NLANES + u] = s;
        s = g_sloc[c*NLANES + u] + g_prod[c*NLANES + u] * s;
    }
}

// pass3: rescan with correct initial state; emit gated y
__global__ void scan_part3(const float* __restrict__ A_log_l,
                           const float* __restrict__ D_l) {
    int t = blockIdx.x * blockDim.x + threadIdx.x;
    int c = t >> 14;
    int u = t & (NLANES-1);
    int n = u & 7;
    int d = (u >> 3) & 1023;
    int b = (u >> 13) & 1;

    float A  = -__expf(A_log_l[d*NS + n]);
    float Dv = D_l[d];
    float s  = g_sst[t];
    int l0 = c * CLEN;
    for (int l = l0; l < l0 + CLEN; l++) {
        int m = b*LL + l;
        float dtv = g_dt[(size_t)m*DIM + d];
        float hsv = g_hs[(size_t)m*DIM + d];
        float Bv  = g_sp[(size_t)m*SPW + RR + n];
        float Cv  = g_sp[(size_t)m*SPW + RR + NS + n];
        float dA  = __expf(dtv * A);
        s = dA * s + (dtv * hsv) * Bv;
        float yv = s * Cv;
        yv += __shfl_xor_sync(0xffffffffu, yv, 1);
        yv += __shfl_xor_sync(0xffffffffu, yv, 2);
        yv += __shfl_xor_sync(0xffffffffu, yv, 4);
        if (n == 0) {
            float g  = g_proj[(size_t)m*DI2 + DIM + d];
            float sg = g / (1.f + __expf(-g));
            g_y[(size_t)m*DIM + d] = (yv + hsv * Dv) * sg;
        }
    }
}

// -------------------- launcher --------------------
extern "C" void kernel_launch(void* const* d_in, const int* in_sizes, int n_in,
                              void* d_out, int out_size)
{
    const int*   x         = (const int*)  d_in[0];
    const float* emb       = (const float*)d_in[1];
    const float* in_proj_w = (const float*)d_in[2];
    const float* conv_w    = (const float*)d_in[3];
    const float* conv_b    = (const float*)d_in[4];
    const float* x_proj_w  = (const float*)d_in[5];
    const float* dt_proj_w = (const float*)d_in[6];
    const float* dt_proj_b = (const float*)d_in[7];
    const float* A_log     = (const float*)d_in[8];
    const float* D_ssm     = (const float*)d_in[9];
    const float* out_proj_w= (const float*)d_in[10];
    const float* norm_w    = (const float*)d_in[11];
    const float* norm_f_w  = (const float*)d_in[12];
    const float* head_w    = (const float*)d_in[13];
    const float* head_b    = (const float*)d_in[14];
    float* out = (float*)d_out;

    cudaFuncSetAttribute(gemm_tc, cudaFuncAttributeMaxDynamicSharedMemorySize, GSMEM);

    float *p_hn, *p_proj, *p_hs, *p_sp, *p_dt, *p_y, *p_h;
    cudaGetSymbolAddress((void**)&p_h,    g_h);
    cudaGetSymbolAddress((void**)&p_hn,   g_hn);
    cudaGetSymbolAddress((void**)&p_proj, g_proj);
    cudaGetSymbolAddress((void**)&p_hs,   g_hs);
    cudaGetSymbolAddress((void**)&p_sp,   g_sp);
    cudaGetSymbolAddress((void**)&p_dt,   g_dt);
    cudaGetSymbolAddress((void**)&p_y,    g_y);

    embed_kernel<<<MM, HH>>>(x, emb);

    for (int l = 0; l < NLAYERS; l++) {
        rmsnorm_kernel<<<MM, 256>>>(norm_w + l*HH);

        // in_proj: [2048,512] x [2048,512]^T -> g_proj [2048,2048]
        gemm_tc<<<dim3(DI2/128, MM/128), 256, GSMEM>>>(
            p_hn, in_proj_w + (size_t)l*DI2*HH, nullptr, nullptr, p_proj,
            MM, DI2, HH, HH, HH, DI2, 0);

        conv_silu_kernel<<<dim3(MM, DIM/256), 256>>>(
            conv_w + (size_t)l*DIM*KC, conv_b + l*DIM);

        // x_proj: [2048,1024] x [48,1024]^T -> g_sp [2048,48]
        gemm_tc<<<dim3(1, MM/128), 256, GSMEM>>>(
            p_hs, x_proj_w + (size_t)l*SPW*DIM, nullptr, nullptr, p_sp,
            MM, SPW, DIM, DIM, DIM, SPW, 0);

        // dt_proj: [2048,32(stride 48)] x [1024,32]^T +bias softplus -> g_dt
        gemm_tc<<<dim3(DIM/128, MM/128), 256, GSMEM>>>(
            p_sp, dt_proj_w + (size_t)l*DIM*RR, dt_proj_b + l*DIM, nullptr, p_dt,
            MM, DIM, RR, SPW, RR, DIM, 1);

        scan_part1<<<(NCHUNK*NLANES)/256, 256>>>(A_log + (size_t)l*DIM*NS);
        scan_part2<<<NLANES/256, 256>>>();
        scan_part3<<<(NCHUNK*NLANES)/256, 256>>>(A_log + (size_t)l*DIM*NS, D_ssm + l*DIM);

        // out_proj + residual: g_h += g_y x [512,1024]^T
        gemm_tc<<<dim3(HH/128, MM/128), 256, GSMEM>>>(
            p_y, out_proj_w + (size_t)l*HH*DIM, nullptr, p_h, p_h,
            MM, HH, DIM, DIM, DIM, HH, 2);
    }

    rmsnorm_kernel<<<MM, 256>>>(norm_f_w);

    // head: [2048,512] x [300,512]^T + bias -> out [2048,300]
    gemm_tc<<<dim3((VMX + 127)/128, MM/128), 256, GSMEM>>>(
        p_hn, head_w, head_b, nullptr, out,
        MM, VMX, HH, HH, HH, VMX, 3);
}

// round 5
// speedup vs baseline: 3.6297x; 1.0788x over previous
#include <cuda_runtime.h>
#include <cuda_bf16.h>
#include <math.h>
#include <stdint.h>

#define BB 2
#define LL 1024
#define HH 512
#define DIM 1024
#define DI2 2048
#define NS 8
#define KC 4
#define RR 32
#define NLAYERS 4
#define VMX 300
#define NFEAT 4
#define MM (BB*LL)          /* 2048 rows */
#define SPW 48              /* R + 2N */
#define EPS 1e-5f

#define NCHUNK 8
#define CLEN (LL/NCHUNK)    /* 128 */
#define NLANES (BB*DIM*NS)  /* 16384 */

typedef __nv_bfloat16 bf16;

// -------------------- scratch (device globals; no allocation) --------------------
__device__ float g_h   [MM*HH];     // residual stream (f32)
__device__ float g_proj[MM*DI2];    // in_proj output (f32; conv + gate)
__device__ float g_hs  [MM*DIM];    // conv+silu (f32; scan)
__device__ float g_sp  [MM*SPW];    // x_proj B/C cols (f32; scan)
__device__ float g_dt  [MM*DIM];    // softplus(dt) (f32; scan)
__device__ float g_sloc[NCHUNK*NLANES];
__device__ float g_prod[NCHUNK*NLANES];
__device__ float g_sst [NCHUNK*NLANES];

// bf16 hi/lo split operands for GEMMs
__device__ bf16 g_hn_h[MM*HH],  g_hn_l[MM*HH];     // rmsnorm out
__device__ bf16 g_hs_h[MM*DIM], g_hs_l[MM*DIM];    // conv out
__device__ bf16 g_dtr_h[MM*RR], g_dtr_l[MM*RR];    // x_proj dt cols
__device__ bf16 g_y_h[MM*DIM],  g_y_l[MM*DIM];     // scan out
// split weights (all layers)
__device__ bf16 g_wi_h[NLAYERS*DI2*HH], g_wi_l[NLAYERS*DI2*HH];
__device__ bf16 g_wx_h[NLAYERS*SPW*DIM], g_wx_l[NLAYERS*SPW*DIM];
__device__ bf16 g_wd_h[NLAYERS*DIM*RR],  g_wd_l[NLAYERS*DIM*RR];
__device__ bf16 g_wo_h[NLAYERS*HH*DIM],  g_wo_l[NLAYERS*HH*DIM];
__device__ bf16 g_wh_h[VMX*HH],          g_wh_l[VMX*HH];

// -------------------- helpers --------------------
__device__ __forceinline__ uint32_t smem_u32(const void* p) {
    return (uint32_t)__cvta_generic_to_shared(p);
}
__device__ __forceinline__ void split1(float v, bf16& h, bf16& l) {
    h = __float2bfloat16_rn(v);
    l = __float2bfloat16_rn(v - __bfloat162float(h));
}
__device__ __forceinline__ void ldsm4(uint32_t* r, uint32_t addr) {
    asm volatile("ldmatrix.sync.aligned.m8n8.x4.shared.b16 {%0,%1,%2,%3}, [%4];"
                 : "=r"(r[0]), "=r"(r[1]), "=r"(r[2]), "=r"(r[3]) : "r"(addr));
}
__device__ __forceinline__ void mma_bf16(float* d, const uint32_t* a, const uint32_t* b) {
    asm volatile(
        "mma.sync.aligned.m16n8k16.row.col.f32.bf16.bf16.f32 "
        "{%0,%1,%2,%3}, {%4,%5,%6,%7}, {%8,%9}, {%0,%1,%2,%3};"
        : "+f"(d[0]), "+f"(d[1]), "+f"(d[2]), "+f"(d[3])
        : "r"(a[0]), "r"(a[1]), "r"(a[2]), "r"(a[3]), "r"(b[0]), "r"(b[1]));
}
__device__ __forceinline__ void cp16(uint32_t dst, const void* src, bool pred) {
    int sz = pred ? 16 : 0;
    asm volatile("cp.async.cg.shared.global [%0], [%1], 16, %2;"
                 :: "r"(dst), "l"(src), "r"(sz) : "memory");
}
#define CP_COMMIT() asm volatile("cp.async.commit_group;" ::: "memory")
#define CP_WAIT(n)  asm volatile("cp.async.wait_group %0;" :: "n"(n) : "memory")

// -------------------- weight split --------------------
__global__ void split_kernel(const float4* __restrict__ src,
                             uint32_t* __restrict__ hi, uint32_t* __restrict__ lo, int n4) {
    int i = blockIdx.x * 256 + threadIdx.x;
    if (i >= n4) return;
    float4 v = src[i];
    bf16 h0,l0,h1,l1,h2,l2,h3,l3;
    split1(v.x, h0, l0); split1(v.y, h1, l1);
    split1(v.z, h2, l2); split1(v.w, h3, l3);
    hi[2*i+0] = ((uint32_t)__bfloat16_as_ushort(h1) << 16) | __bfloat16_as_ushort(h0);
    hi[2*i+1] = ((uint32_t)__bfloat16_as_ushort(h3) << 16) | __bfloat16_as_ushort(h2);
    lo[2*i+0] = ((uint32_t)__bfloat16_as_ushort(l1) << 16) | __bfloat16_as_ushort(l0);
    lo[2*i+1] = ((uint32_t)__bfloat16_as_ushort(l3) << 16) | __bfloat16_as_ushort(l2);
}

// ==================== GEMM: C = A * B^T (+epilogue), bf16 hi/lo inputs ====================
// A_hi/lo: [M,K] bf16 (lda), B_hi/lo: [N,K] bf16 (ldb), C: [M,N] f32 (ldc)
// 128x128 CTA tile, 256 thr, 8 warps (4M x 2N, warp 32x64). K-chunk 32, 4-stage cp.async.
// mode 0: store ; 1: +bias softplus ; 2: +resid ; 3: +bias ; 4: x_proj (dtr split + sp f32)
#define KCH 32
#define SSTB 80                 /* bytes per smem row (40 bf16), 16B-aligned, ldsm conflict-free */
#define TILEB (128*SSTB)        /* 10240 B */
#define STAGEB (4*TILEB)        /* 40960 B */
#define NSTAGE 4
#define GSMEM (NSTAGE*STAGEB)   /* 163840 B */

__device__ __forceinline__ void load_stage(
    uint32_t sbase, const bf16* Ah, const bf16* Al, const bf16* Bh, const bf16* Bl,
    int bm, int bn, int k0, int lda, int ldb, int Ndim, int tid)
{
#pragma unroll
    for (int i = 0; i < 2; i++) {
        int idx = tid + i*256;
        int row = idx >> 2;          // 0..127
        int c4  = idx & 3;           // 16B chunk within 64B row-slab
        uint32_t doff = (uint32_t)row * SSTB + (uint32_t)c4 * 16;
        size_t aoff = (size_t)(bm + row) * lda + k0 + c4*8;
        cp16(sbase + doff,           Ah + aoff, true);
        cp16(sbase + TILEB + doff,   Al + aoff, true);
        bool bp = (bn + row) < Ndim;
        int brow = bp ? (bn + row) : 0;
        size_t boff = (size_t)brow * ldb + k0 + c4*8;
        cp16(sbase + 2*TILEB + doff, Bh + boff, bp);
        cp16(sbase + 3*TILEB + doff, Bl + boff, bp);
    }
}

__global__ __launch_bounds__(256, 1)
void gemm_tc(const bf16* __restrict__ Ah, const bf16* __restrict__ Al,
             const bf16* __restrict__ Bh, const bf16* __restrict__ Bl,
             const float* __restrict__ bias, const float* __restrict__ resid,
             float* __restrict__ C, bf16* __restrict__ oHi, bf16* __restrict__ oLo,
             int Mdim, int Ndim, int Kdim,
             int lda, int ldb, int ldc, int mode)
{
    extern __shared__ char sm[];
    const int tid  = threadIdx.x;
    const int lane = tid & 31;
    const int wid  = tid >> 5;
    const int warpM = wid & 3;
    const int warpN = wid >> 2;
    const int bm = blockIdx.y * 128;
    const int bn = blockIdx.x * 128;

    float acc[2][8][4];
#pragma unroll
    for (int i = 0; i < 2; i++)
#pragma unroll
        for (int j = 0; j < 8; j++)
#pragma unroll
            for (int q = 0; q < 4; q++) acc[i][j][q] = 0.f;

    const int nch = Kdim / KCH;
    const uint32_t sb0 = smem_u32(sm);

    // prologue: issue NSTAGE-1 stages
#pragma unroll
    for (int s = 0; s < NSTAGE-1; s++) {
        if (s < nch)
            load_stage(sb0 + (uint32_t)s*STAGEB, Ah, Al, Bh, Bl, bm, bn, s*KCH, lda, ldb, Ndim, tid);
        CP_COMMIT();
    }

    for (int ci = 0; ci < nch; ci++) {
        int pf = ci + NSTAGE - 1;
        if (pf < nch)
            load_stage(sb0 + (uint32_t)(pf % NSTAGE)*STAGEB, Ah, Al, Bh, Bl, bm, bn, pf*KCH, lda, ldb, Ndim, tid);
        CP_COMMIT();
        CP_WAIT(NSTAGE-1);
        __syncthreads();

        const uint32_t uAh = sb0 + (uint32_t)(ci % NSTAGE)*STAGEB;
        const uint32_t uAl = uAh + TILEB;
        const uint32_t uBh = uAh + 2*TILEB;
        const uint32_t uBl = uAh + 3*TILEB;

#pragma unroll
        for (int ks = 0; ks < 2; ks++) {
            uint32_t afh[2][4], afl[2][4], bfh[8][2], bfl[8][2];
            const int kcA = ks*16 + (lane >> 4) * 8;
            const int rA0 = warpM*32 + (lane & 15);
#pragma unroll
            for (int mi = 0; mi < 2; mi++) {
                uint32_t off = (uint32_t)(rA0 + mi*16) * SSTB + (uint32_t)kcA * 2;
                ldsm4(afh[mi], uAh + off);
                ldsm4(afl[mi], uAl + off);
            }
            const int rB0 = warpN*64 + (lane & 7) + ((lane >> 4) << 3);
            const int kcB = ks*16 + ((lane >> 3) & 1) * 8;
#pragma unroll
            for (int g = 0; g < 4; g++) {
                uint32_t off = (uint32_t)(rB0 + g*16) * SSTB + (uint32_t)kcB * 2;
                uint32_t t4[4];
                ldsm4(t4, uBh + off);
                bfh[2*g][0]=t4[0]; bfh[2*g][1]=t4[1]; bfh[2*g+1][0]=t4[2]; bfh[2*g+1][1]=t4[3];
                ldsm4(t4, uBl + off);
                bfl[2*g][0]=t4[0]; bfl[2*g][1]=t4[1]; bfl[2*g+1][0]=t4[2]; bfl[2*g+1][1]=t4[3];
            }
#pragma unroll
            for (int mi = 0; mi < 2; mi++)
#pragma unroll
                for (int g = 0; g < 8; g++) {
                    mma_bf16(acc[mi][g], afh[mi], bfh[g]);
                    mma_bf16(acc[mi][g], afh[mi], bfl[g]);
                    mma_bf16(acc[mi][g], afl[mi], bfh[g]);
                }
        }
        __syncthreads();
    }

    // epilogue
#pragma unroll
    for (int mi = 0; mi < 2; mi++) {
        const int row0 = bm + warpM*32 + mi*16 + (lane >> 2);
#pragma unroll
        for (int g = 0; g < 8; g++) {
            const int col = bn + warpN*64 + g*8 + (lane & 3)*2;
            if (col >= Ndim) continue;
#pragma unroll
            for (int h = 0; h < 2; h++) {
                const int r = row0 + h*8;
                float v0 = acc[mi][g][2*h+0];
                float v1 = acc[mi][g][2*h+1];
                if (mode == 1) {
                    v0 += bias[col]; v1 += bias[col+1];
                    v0 = (v0 > 20.f) ? v0 : log1pf(expf(v0));
                    v1 = (v1 > 20.f) ? v1 : log1pf(expf(v1));
                } else if (mode == 2) {
                    const float2 rr = *reinterpret_cast<const float2*>(resid + (size_t)r*ldc + col);
                    v0 += rr.x; v1 += rr.y;
                } else if (mode == 3) {
                    v0 += bias[col]; v1 += bias[col+1];
                } else if (mode == 4) {
                    if (col < RR) {
                        bf16 h0,l0,h1,l1;
                        split1(v0, h0, l0); split1(v1, h1, l1);
                        *reinterpret_cast<uint32_t*>(oHi + (size_t)r*RR + col) =
                            ((uint32_t)__bfloat16_as_ushort(h1) << 16) | __bfloat16_as_ushort(h0);
                        *reinterpret_cast<uint32_t*>(oLo + (size_t)r*RR + col) =
                            ((uint32_t)__bfloat16_as_ushort(l1) << 16) | __bfloat16_as_ushort(l0);
                    } else if (col < SPW) {
                        *reinterpret_cast<float2*>(C + (size_t)r*ldc + col) = make_float2(v0, v1);
                    }
                    continue;
                }
                *reinterpret_cast<float2*>(C + (size_t)r*ldc + col) = make_float2(v0, v1);
            }
        }
    }
}

// -------------------- embedding --------------------
__global__ void embed_kernel(const int* __restrict__ x, const float* __restrict__ emb) {
    int m = blockIdx.x;
    int t = threadIdx.x;
    float s = 0.f;
#pragma unroll
    for (int i = 0; i < NFEAT; i++) {
        int v = x[m*NFEAT + i];
        s += emb[((size_t)i*VMX + v)*HH + t];
    }
    g_h[(size_t)m*HH + t] = s;
}

// -------------------- rmsnorm -> bf16 hi/lo --------------------
__global__ void rmsnorm_kernel(const float* __restrict__ w) {
    int m = blockIdx.x;
    int tid = threadIdx.x;
    const float* row = g_h + (size_t)m*HH;
    float s = 0.f;
    for (int i = tid; i < HH; i += 256) { float v = row[i]; s += v*v; }
    __shared__ float red[256];
    red[tid] = s; __syncthreads();
    for (int st = 128; st > 0; st >>= 1) {
        if (tid < st) red[tid] += red[tid + st];
        __syncthreads();
    }
    float r = rsqrtf(red[0] * (1.f/HH) + EPS);
    for (int i = tid; i < HH; i += 256) {
        float v = row[i] * r * w[i];
        bf16 h, l; split1(v, h, l);
        g_hn_h[(size_t)m*HH + i] = h;
        g_hn_l[(size_t)m*HH + i] = l;
    }
}

// -------------------- causal depthwise conv (K=4) + silu --------------------
__global__ void conv_silu_kernel(const float* __restrict__ cw, const float* __restrict__ cb) {
    int m = blockIdx.x;
    int d = blockIdx.y * 256 + threadIdx.x;
    int b = m / LL, l = m % LL;
    float c = cb[d];
#pragma unroll
    for (int k = 0; k < KC; k++) {
        int li = l - (KC - 1) + k;
        if (li >= 0)
            c += g_proj[((size_t)(b*LL + li))*DI2 + d] * cw[d*KC + k];
    }
    float s = c / (1.f + __expf(-c));
    g_hs[(size_t)m*DIM + d] = s;
    bf16 h, lo; split1(s, h, lo);
    g_hs_h[(size_t)m*DIM + d] = h;
    g_hs_l[(size_t)m*DIM + d] = lo;
}

// -------------------- chunked selective scan --------------------
__global__ void scan_part1(const float* __restrict__ A_log_l) {
    int t = blockIdx.x * blockDim.x + threadIdx.x;
    int c = t >> 14;
    int u = t & (NLANES-1);
    int n = u & 7;
    int d = (u >> 3) & 1023;
    int b = (u >> 13) & 1;

    float A = -__expf(A_log_l[d*NS + n]);
    float s = 0.f, P = 1.f;
    int l0 = c * CLEN;
    for (int l = l0; l < l0 + CLEN; l++) {
        int m = b*LL + l;
        float dtv = g_dt[(size_t)m*DIM + d];
        float hsv = g_hs[(size_t)m*DIM + d];
        float Bv  = g_sp[(size_t)m*SPW + RR + n];
        float dA  = __expf(dtv * A);
        s = dA * s + (dtv * hsv) * Bv;
        P *= dA;
    }
    g_sloc[t] = s;
    g_prod[t] = P;
}

__global__ void scan_part2() {
    int u = blockIdx.x * blockDim.x + threadIdx.x;
    float s = 0.f;
#pragma unroll
    for (int c = 0; c < NCHUNK; c++) {
        g_sst[c*NLANES + u] = s;
        s = g_sloc[c*NLANES + u] + g_prod[c*NLANES + u] * s;
    }
}

__global__ void scan_part3(const float* __restrict__ A_log_l,
                           const float* __restrict__ D_l) {
    int t = blockIdx.x * blockDim.x + threadIdx.x;
    int c = t >> 14;
    int u = t & (NLANES-1);
    int n = u & 7;
    int d = (u >> 3) & 1023;
    int b = (u >> 13) & 1;

    float A  = -__expf(A_log_l[d*NS + n]);
    float Dv = D_l[d];
    float s  = g_sst[t];
    int l0 = c * CLEN;
    for (int l = l0; l < l0 + CLEN; l++) {
        int m = b*LL + l;
        float dtv = g_dt[(size_t)m*DIM + d];
        float hsv = g_hs[(size_t)m*DIM + d];
        float Bv  = g_sp[(size_t)m*SPW + RR + n];
        float Cv  = g_sp[(size_t)m*SPW + RR + NS + n];
        float dA  = __expf(dtv * A);
        s = dA * s + (dtv * hsv) * Bv;
        float yv = s * Cv;
        yv += __shfl_xor_sync(0xffffffffu, yv, 1);
        yv += __shfl_xor_sync(0xffffffffu, yv, 2);
        yv += __shfl_xor_sync(0xffffffffu, yv, 4);
        if (n == 0) {
            float g  = g_proj[(size_t)m*DI2 + DIM + d];
            float sg = g / (1.f + __expf(-g));
            float yo = (yv + hsv * Dv) * sg;
            bf16 h, lo; split1(yo, h, lo);
            g_y_h[(size_t)m*DIM + d] = h;
            g_y_l[(size_t)m*DIM + d] = lo;
        }
    }
}

// -------------------- launcher --------------------
extern "C" void kernel_launch(void* const* d_in, const int* in_sizes, int n_in,
                              void* d_out, int out_size)
{
    const int*   x         = (const int*)  d_in[0];
    const float* emb       = (const float*)d_in[1];
    const float* in_proj_w = (const float*)d_in[2];
    const float* conv_w    = (const float*)d_in[3];
    const float* conv_b    = (const float*)d_in[4];
    const float* x_proj_w  = (const float*)d_in[5];
    const float* dt_proj_w = (const float*)d_in[6];
    const float* dt_proj_b = (const float*)d_in[7];
    const float* A_log     = (const float*)d_in[8];
    const float* D_ssm     = (const float*)d_in[9];
    const float* out_proj_w= (const float*)d_in[10];
    const float* norm_w    = (const float*)d_in[11];
    const float* norm_f_w  = (const float*)d_in[12];
    const float* head_w    = (const float*)d_in[13];
    const float* head_b    = (const float*)d_in[14];
    float* out = (float*)d_out;

    cudaFuncSetAttribute(gemm_tc, cudaFuncAttributeMaxDynamicSharedMemorySize, GSMEM);

    float *p_h, *p_proj, *p_sp, *p_dt;
    cudaGetSymbolAddress((void**)&p_h,    g_h);
    cudaGetSymbolAddress((void**)&p_proj, g_proj);
    cudaGetSymbolAddress((void**)&p_sp,   g_sp);
    cudaGetSymbolAddress((void**)&p_dt,   g_dt);

    bf16 *p_hn_h,*p_hn_l,*p_hs_h,*p_hs_l,*p_dtr_h,*p_dtr_l,*p_y_h,*p_y_l;
    bf16 *p_wi_h,*p_wi_l,*p_wx_h,*p_wx_l,*p_wd_h,*p_wd_l,*p_wo_h,*p_wo_l,*p_wh_h,*p_wh_l;
    cudaGetSymbolAddress((void**)&p_hn_h, g_hn_h);  cudaGetSymbolAddress((void**)&p_hn_l, g_hn_l);
    cudaGetSymbolAddress((void**)&p_hs_h, g_hs_h);  cudaGetSymbolAddress((void**)&p_hs_l, g_hs_l);
    cudaGetSymbolAddress((void**)&p_dtr_h, g_dtr_h); cudaGetSymbolAddress((void**)&p_dtr_l, g_dtr_l);
    cudaGetSymbolAddress((void**)&p_y_h,  g_y_h);   cudaGetSymbolAddress((void**)&p_y_l,  g_y_l);
    cudaGetSymbolAddress((void**)&p_wi_h, g_wi_h);  cudaGetSymbolAddress((void**)&p_wi_l, g_wi_l);
    cudaGetSymbolAddress((void**)&p_wx_h, g_wx_h);  cudaGetSymbolAddress((void**)&p_wx_l, g_wx_l);
    cudaGetSymbolAddress((void**)&p_wd_h, g_wd_h);  cudaGetSymbolAddress((void**)&p_wd_l, g_wd_l);
    cudaGetSymbolAddress((void**)&p_wo_h, g_wo_h);  cudaGetSymbolAddress((void**)&p_wo_l, g_wo_l);
    cudaGetSymbolAddress((void**)&p_wh_h, g_wh_h);  cudaGetSymbolAddress((void**)&p_wh_l, g_wh_l);

    // ---- split weights (per call; constant inputs -> deterministic) ----
    {
        int n4;
        n4 = NLAYERS*DI2*HH/4;
        split_kernel<<<(n4+255)/256, 256>>>((const float4*)in_proj_w, (uint32_t*)p_wi_h, (uint32_t*)p_wi_l, n4);
        n4 = NLAYERS*SPW*DIM/4;
        split_kernel<<<(n4+255)/256, 256>>>((const float4*)x_proj_w, (uint32_t*)p_wx_h, (uint32_t*)p_wx_l, n4);
        n4 = NLAYERS*DIM*RR/4;
        split_kernel<<<(n4+255)/256, 256>>>((const float4*)dt_proj_w, (uint32_t*)p_wd_h, (uint32_t*)p_wd_l, n4);
        n4 = NLAYERS*HH*DIM/4;
        split_kernel<<<(n4+255)/256, 256>>>((const float4*)out_proj_w, (uint32_t*)p_wo_h, (uint32_t*)p_wo_l, n4);
        n4 = VMX*HH/4;
        split_kernel<<<(n4+255)/256, 256>>>((const float4*)head_w, (uint32_t*)p_wh_h, (uint32_t*)p_wh_l, n4);
    }

    embed_kernel<<<MM, HH>>>(x, emb);

    for (int l = 0; l < NLAYERS; l++) {
        rmsnorm_kernel<<<MM, 256>>>(norm_w + l*HH);

        // in_proj: hn[2048,512] x w_in[2048,512]^T -> g_proj f32
        gemm_tc<<<dim3(DI2/128, MM/128), 256, GSMEM>>>(
            p_hn_h, p_hn_l, p_wi_h + (size_t)l*DI2*HH, p_wi_l + (size_t)l*DI2*HH,
            nullptr, nullptr, p_proj, nullptr, nullptr,
            MM, DI2, HH, HH, HH, DI2, 0);

        conv_silu_kernel<<<dim3(MM, DIM/256), 256>>>(
            conv_w + (size_t)l*DIM*KC, conv_b + l*DIM);

        // x_proj: hs[2048,1024] x w_x[48,1024]^T -> dtr hi/lo + g_sp f32
        gemm_tc<<<dim3(1, MM/128), 256, GSMEM>>>(
            p_hs_h, p_hs_l, p_wx_h + (size_t)l*SPW*DIM, p_wx_l + (size_t)l*SPW*DIM,
            nullptr, nullptr, p_sp, p_dtr_h, p_dtr_l,
            MM, SPW, DIM, DIM, DIM, SPW, 4);

        // dt_proj: dtr[2048,32] x w_dt[1024,32]^T +bias softplus -> g_dt f32
        gemm_tc<<<dim3(DIM/128, MM/128), 256, GSMEM>>>(
            p_dtr_h, p_dtr_l, p_wd_h + (size_t)l*DIM*RR, p_wd_l + (size_t)l*DIM*RR,
            dt_proj_b + l*DIM, nullptr, p_dt, nullptr, nullptr,
            MM, DIM, RR, RR, RR, DIM, 1);

        scan_part1<<<(NCHUNK*NLANES)/256, 256>>>(A_log + (size_t)l*DIM*NS);
        scan_part2<<<NLANES/256, 256>>>();
        scan_part3<<<(NCHUNK*NLANES)/256, 256>>>(A_log + (size_t)l*DIM*NS, D_ssm + l*DIM);

        // out_proj + residual: g_h += y[2048,1024] x w_out[512,1024]^T
        gemm_tc<<<dim3(HH/128, MM/128), 256, GSMEM>>>(
            p_y_h, p_y_l, p_wo_h + (size_t)l*HH*DIM, p_wo_l + (size_t)l*HH*DIM,
            nullptr, p_h, p_h, nullptr, nullptr,
            MM, HH, DIM, DIM, DIM, HH, 2);
    }

    rmsnorm_kernel<<<MM, 256>>>(norm_f_w);

    // head: hn[2048,512] x w_head[300,512]^T + bias -> out [2048,300]
    gemm_tc<<<dim3((VMX + 127)/128, MM/128), 256, GSMEM>>>(
        p_hn_h, p_hn_l, p_wh_h, p_wh_l,
        head_b, nullptr, out, nullptr, nullptr,
        MM, VMX, HH, HH, HH, VMX, 3);
}

// round 6
// speedup vs baseline: 4.8051x; 1.3238x over previous
#include <cuda_runtime.h>
#include <cuda_bf16.h>
#include <math.h>
#include <stdint.h>

#define BB 2
#define LL 1024
#define HH 512
#define DIM 1024
#define DI2 2048
#define NS 8
#define KC 4
#define RR 32
#define NLAYERS 4
#define VMX 300
#define NFEAT 4
#define MM (BB*LL)          /* 2048 rows */
#define SPW 48              /* R + 2N */
#define EPS 1e-5f

#define NCHUNK 16
#define CLEN (LL/NCHUNK)    /* 64 */
#define NLANES (BB*DIM*NS)  /* 16384 */

typedef __nv_bfloat16 bf16;

// -------------------- scratch (device globals; no allocation) --------------------
__device__ float g_h   [MM*HH];     // residual stream (f32)
__device__ float g_proj[MM*DI2];    // in_proj output (f32; conv + gate)
__device__ float g_hs  [MM*DIM];    // conv+silu (f32; scan)
__device__ float g_sp  [MM*SPW];    // x_proj output (f32)
__device__ float g_dt  [MM*DIM];    // softplus(dt) (f32; scan)
__device__ float g_sloc[NCHUNK*NLANES];
__device__ float g_prod[NCHUNK*NLANES];
__device__ float g_sst [NCHUNK*NLANES];

// bf16 hi/lo split operands for GEMMs
__device__ bf16 g_hn_h[MM*HH],  g_hn_l[MM*HH];
__device__ bf16 g_hs_h[MM*DIM], g_hs_l[MM*DIM];
__device__ bf16 g_dtr_h[MM*RR], g_dtr_l[MM*RR];
__device__ bf16 g_y_h[MM*DIM],  g_y_l[MM*DIM];
// split weights
__device__ bf16 g_wi_h[NLAYERS*DI2*HH], g_wi_l[NLAYERS*DI2*HH];
__device__ bf16 g_wx_h[NLAYERS*SPW*DIM], g_wx_l[NLAYERS*SPW*DIM];
__device__ bf16 g_wd_h[NLAYERS*DIM*RR],  g_wd_l[NLAYERS*DIM*RR];
__device__ bf16 g_wo_h[NLAYERS*HH*DIM],  g_wo_l[NLAYERS*HH*DIM];
__device__ bf16 g_wh_h[VMX*HH],          g_wh_l[VMX*HH];

// -------------------- helpers --------------------
__device__ __forceinline__ uint32_t smem_u32(const void* p) {
    return (uint32_t)__cvta_generic_to_shared(p);
}
__device__ __forceinline__ void split1(float v, bf16& h, bf16& l) {
    h = __float2bfloat16_rn(v);
    l = __float2bfloat16_rn(v - __bfloat162float(h));
}
__device__ __forceinline__ void ldsm4(uint32_t* r, uint32_t addr) {
    asm volatile("ldmatrix.sync.aligned.m8n8.x4.shared.b16 {%0,%1,%2,%3}, [%4];"
                 : "=r"(r[0]), "=r"(r[1]), "=r"(r[2]), "=r"(r[3]) : "r"(addr));
}
__device__ __forceinline__ void mma_bf16(float* d, const uint32_t* a, const uint32_t* b) {
    asm volatile(
        "mma.sync.aligned.m16n8k16.row.col.f32.bf16.bf16.f32 "
        "{%0,%1,%2,%3}, {%4,%5,%6,%7}, {%8,%9}, {%0,%1,%2,%3};"
        : "+f"(d[0]), "+f"(d[1]), "+f"(d[2]), "+f"(d[3])
        : "r"(a[0]), "r"(a[1]), "r"(a[2]), "r"(a[3]), "r"(b[0]), "r"(b[1]));
}
__device__ __forceinline__ void cp16(uint32_t dst, const void* src, bool pred) {
    int sz = pred ? 16 : 0;
    asm volatile("cp.async.cg.shared.global [%0], [%1], 16, %2;"
                 :: "r"(dst), "l"(src), "r"(sz) : "memory");
}
#define CP_COMMIT() asm volatile("cp.async.commit_group;" ::: "memory")
#define CP_WAIT(n)  asm volatile("cp.async.wait_group %0;" :: "n"(n) : "memory")

// -------------------- weight split --------------------
__global__ void split_kernel(const float4* __restrict__ src,
                             uint32_t* __restrict__ hi, uint32_t* __restrict__ lo, int n4) {
    int i = blockIdx.x * 256 + threadIdx.x;
    if (i >= n4) return;
    float4 v = src[i];
    bf16 h0,l0,h1,l1,h2,l2,h3,l3;
    split1(v.x, h0, l0); split1(v.y, h1, l1);
    split1(v.z, h2, l2); split1(v.w, h3, l3);
    hi[2*i+0] = ((uint32_t)__bfloat16_as_ushort(h1) << 16) | __bfloat16_as_ushort(h0);
    hi[2*i+1] = ((uint32_t)__bfloat16_as_ushort(h3) << 16) | __bfloat16_as_ushort(h2);
    lo[2*i+0] = ((uint32_t)__bfloat16_as_ushort(l1) << 16) | __bfloat16_as_ushort(l0);
    lo[2*i+1] = ((uint32_t)__bfloat16_as_ushort(l3) << 16) | __bfloat16_as_ushort(l2);
}

// split dt-rank cols of g_sp -> dtr hi/lo (2048 x 32)
__global__ void split_dtr_kernel() {
    int i = blockIdx.x * 256 + threadIdx.x;   // 0 .. 2048*8-1 (float4 units)
    int m  = i >> 3;
    int c4 = (i & 7) * 4;
    float4 v = *reinterpret_cast<const float4*>(&g_sp[(size_t)m*SPW + c4]);
    bf16 h0,l0,h1,l1,h2,l2,h3,l3;
    split1(v.x, h0, l0); split1(v.y, h1, l1);
    split1(v.z, h2, l2); split1(v.w, h3, l3);
    uint32_t* hp = reinterpret_cast<uint32_t*>(&g_dtr_h[(size_t)m*RR + c4]);
    uint32_t* lp = reinterpret_cast<uint32_t*>(&g_dtr_l[(size_t)m*RR + c4]);
    hp[0] = ((uint32_t)__bfloat16_as_ushort(h1) << 16) | __bfloat16_as_ushort(h0);
    hp[1] = ((uint32_t)__bfloat16_as_ushort(h3) << 16) | __bfloat16_as_ushort(h2);
    lp[0] = ((uint32_t)__bfloat16_as_ushort(l1) << 16) | __bfloat16_as_ushort(l0);
    lp[1] = ((uint32_t)__bfloat16_as_ushort(l3) << 16) | __bfloat16_as_ushort(l2);
}

// init out with broadcast bias (head)
__global__ void init_bias_kernel(float* __restrict__ out, const float* __restrict__ b, int n) {
    int i = blockIdx.x * 256 + threadIdx.x;
    if (i < n) out[i] = b[i % VMX];
}

// ==================== GEMM: C (+)= A * B^T, bf16 hi/lo inputs ====================
// 128x128 CTA tile, 256 thr, 8 warps (4M x 2N). K-chunk 32, 2-stage cp.async, 2 CTA/SM.
// blockIdx.z = split-K slice; Kdim = slice length; kOff = z*Kdim.
// mode 0: store ; 1: +bias softplus ; 2: +resid store ; 3: +bias store ; 5: atomicAdd
#define KCH 32
#define SSTB 80                 /* bytes per smem row (40 bf16) */
#define TILEB (128*SSTB)        /* 10240 B */
#define STAGEB (4*TILEB)        /* 40960 B */
#define NSTAGE 2
#define GSMEM (NSTAGE*STAGEB)   /* 81920 B */

__device__ __forceinline__ void load_stage(
    uint32_t sbase, const bf16* Ah, const bf16* Al, const bf16* Bh, const bf16* Bl,
    int bm, int bn, int k0, int lda, int ldb, int Ndim, int tid)
{
#pragma unroll
    for (int i = 0; i < 2; i++) {
        int idx = tid + i*256;
        int row = idx >> 2;
        int c4  = idx & 3;
        uint32_t doff = (uint32_t)row * SSTB + (uint32_t)c4 * 16;
        size_t aoff = (size_t)(bm + row) * lda + k0 + c4*8;
        cp16(sbase + doff,           Ah + aoff, true);
        cp16(sbase + TILEB + doff,   Al + aoff, true);
        bool bp = (bn + row) < Ndim;
        int brow = bp ? (bn + row) : 0;
        size_t boff = (size_t)brow * ldb + k0 + c4*8;
        cp16(sbase + 2*TILEB + doff, Bh + boff, bp);
        cp16(sbase + 3*TILEB + doff, Bl + boff, bp);
    }
}

__global__ __launch_bounds__(256, 2)
void gemm_tc(const bf16* __restrict__ Ah, const bf16* __restrict__ Al,
             const bf16* __restrict__ Bh, const bf16* __restrict__ Bl,
             const float* __restrict__ bias, const float* __restrict__ resid,
             float* __restrict__ C,
             int Mdim, int Ndim, int Kdim,
             int lda, int ldb, int ldc, int mode)
{
    extern __shared__ char sm[];
    const int tid  = threadIdx.x;
    const int lane = tid & 31;
    const int wid  = tid >> 5;
    const int warpM = wid & 3;
    const int warpN = wid >> 2;
    const int bm = blockIdx.y * 128;
    const int bn = blockIdx.x * 128;
    const int kOff = blockIdx.z * Kdim;

    float acc[2][8][4];
#pragma unroll
    for (int i = 0; i < 2; i++)
#pragma unroll
        for (int j = 0; j < 8; j++)
#pragma unroll
            for (int q = 0; q < 4; q++) acc[i][j][q] = 0.f;

    const int nch = Kdim / KCH;
    const uint32_t sb0 = smem_u32(sm);

    load_stage(sb0, Ah, Al, Bh, Bl, bm, bn, kOff, lda, ldb, Ndim, tid);
    CP_COMMIT();

    for (int ci = 0; ci < nch; ci++) {
        if (ci + 1 < nch)
            load_stage(sb0 + (uint32_t)((ci+1) & 1)*STAGEB, Ah, Al, Bh, Bl,
                       bm, bn, kOff + (ci+1)*KCH, lda, ldb, Ndim, tid);
        CP_COMMIT();
        CP_WAIT(1);
        __syncthreads();

        const uint32_t uAh = sb0 + (uint32_t)(ci & 1)*STAGEB;
        const uint32_t uAl = uAh + TILEB;
        const uint32_t uBh = uAh + 2*TILEB;
        const uint32_t uBl = uAh + 3*TILEB;

#pragma unroll
        for (int ks = 0; ks < 2; ks++) {
            uint32_t afh[2][4], afl[2][4];
            const int kcA = ks*16 + (lane >> 4) * 8;
            const int rA0 = warpM*32 + (lane & 15);
#pragma unroll
            for (int mi = 0; mi < 2; mi++) {
                uint32_t off = (uint32_t)(rA0 + mi*16) * SSTB + (uint32_t)kcA * 2;
                ldsm4(afh[mi], uAh + off);
                ldsm4(afl[mi], uAl + off);
            }
            const int rB0 = warpN*64 + (lane & 7) + ((lane >> 4) << 3);
            const int kcB = ks*16 + ((lane >> 3) & 1) * 8;
#pragma unroll
            for (int g2 = 0; g2 < 4; g2++) {
                uint32_t off = (uint32_t)(rB0 + g2*16) * SSTB + (uint32_t)kcB * 2;
                uint32_t th[4], tl[4];
                ldsm4(th, uBh + off);
                ldsm4(tl, uBl + off);
#pragma unroll
                for (int mi = 0; mi < 2; mi++) {
                    mma_bf16(acc[mi][2*g2],   afh[mi], th);
                    mma_bf16(acc[mi][2*g2],   afh[mi], tl);
                    mma_bf16(acc[mi][2*g2],   afl[mi], th);
                    mma_bf16(acc[mi][2*g2+1], afh[mi], th+2);
                    mma_bf16(acc[mi][2*g2+1], afh[mi], tl+2);
                    mma_bf16(acc[mi][2*g2+1], afl[mi], th+2);
                }
            }
        }
        __syncthreads();
    }

    // epilogue
#pragma unroll
    for (int mi = 0; mi < 2; mi++) {
        const int row0 = bm + warpM*32 + mi*16 + (lane >> 2);
#pragma unroll
        for (int g = 0; g < 8; g++) {
            const int col = bn + warpN*64 + g*8 + (lane & 3)*2;
            if (col >= Ndim) continue;
#pragma unroll
            for (int h = 0; h < 2; h++) {
                const int r = row0 + h*8;
                float v0 = acc[mi][g][2*h+0];
                float v1 = acc[mi][g][2*h+1];
                if (mode == 5) {
                    atomicAdd(C + (size_t)r*ldc + col,     v0);
                    if (col + 1 < Ndim) atomicAdd(C + (size_t)r*ldc + col + 1, v1);
                    continue;
                }
                if (mode == 1) {
                    v0 += bias[col]; v1 += bias[col+1];
                    v0 = (v0 > 20.f) ? v0 : log1pf(expf(v0));
                    v1 = (v1 > 20.f) ? v1 : log1pf(expf(v1));
                } else if (mode == 2) {
                    const float2 rr = *reinterpret_cast<const float2*>(resid + (size_t)r*ldc + col);
                    v0 += rr.x; v1 += rr.y;
                } else if (mode == 3) {
                    v0 += bias[col]; v1 += bias[col+1];
                }
                *reinterpret_cast<float2*>(C + (size_t)r*ldc + col) = make_float2(v0, v1);
            }
        }
    }
}

// -------------------- embedding --------------------
__global__ void embed_kernel(const int* __restrict__ x, const float* __restrict__ emb) {
    int m = blockIdx.x;
    int t = threadIdx.x;
    float s = 0.f;
#pragma unroll
    for (int i = 0; i < NFEAT; i++) {
        int v = x[m*NFEAT + i];
        s += emb[((size_t)i*VMX + v)*HH + t];
    }
    g_h[(size_t)m*HH + t] = s;
}

// -------------------- rmsnorm -> bf16 hi/lo --------------------
__global__ void rmsnorm_kernel(const float* __restrict__ w) {
    int m = blockIdx.x;
    int tid = threadIdx.x;
    const float* row = g_h + (size_t)m*HH;
    float s = 0.f;
    for (int i = tid; i < HH; i += 256) { float v = row[i]; s += v*v; }
    __shared__ float red[256];
    red[tid] = s; __syncthreads();
    for (int st = 128; st > 0; st >>= 1) {
        if (tid < st) red[tid] += red[tid + st];
        __syncthreads();
    }
    float r = rsqrtf(red[0] * (1.f/HH) + EPS);
    for (int i = tid; i < HH; i += 256) {
        float v = row[i] * r * w[i];
        bf16 h, l; split1(v, h, l);
        g_hn_h[(size_t)m*HH + i] = h;
        g_hn_l[(size_t)m*HH + i] = l;
    }
}

// -------------------- causal depthwise conv (K=4) + silu --------------------
__global__ void conv_silu_kernel(const float* __restrict__ cw, const float* __restrict__ cb) {
    int m = blockIdx.x;
    int d = blockIdx.y * 256 + threadIdx.x;
    int b = m / LL, l = m % LL;
    float c = cb[d];
#pragma unroll
    for (int k = 0; k < KC; k++) {
        int li = l - (KC - 1) + k;
        if (li >= 0)
            c += g_proj[((size_t)(b*LL + li))*DI2 + d] * cw[d*KC + k];
    }
    float s = c / (1.f + __expf(-c));
    g_hs[(size_t)m*DIM + d] = s;
    bf16 h, lo; split1(s, h, lo);
    g_hs_h[(size_t)m*DIM + d] = h;
    g_hs_l[(size_t)m*DIM + d] = lo;
}

// -------------------- chunked selective scan --------------------
__global__ void scan_part1(const float* __restrict__ A_log_l) {
    int t = blockIdx.x * blockDim.x + threadIdx.x;
    int c = t >> 14;
    int u = t & (NLANES-1);
    int n = u & 7;
    int d = (u >> 3) & 1023;
    int b = (u >> 13) & 1;

    float A = -__expf(A_log_l[d*NS + n]);
    float s = 0.f, P = 1.f;
    int l0 = c * CLEN;
    for (int l = l0; l < l0 + CLEN; l++) {
        int m = b*LL + l;
        float dtv = g_dt[(size_t)m*DIM + d];
        float hsv = g_hs[(size_t)m*DIM + d];
        float Bv  = g_sp[(size_t)m*SPW + RR + n];
        float dA  = __expf(dtv * A);
        s = dA * s + (dtv * hsv) * Bv;
        P *= dA;
    }
    g_sloc[t] = s;
    g_prod[t] = P;
}

__global__ void scan_part2() {
    int u = blockIdx.x * blockDim.x + threadIdx.x;
    float s = 0.f;
#pragma unroll
    for (int c = 0; c < NCHUNK; c++) {
        g_sst[c*NLANES + u] = s;
        s = g_sloc[c*NLANES + u] + g_prod[c*NLANES + u] * s;
    }
}

__global__ void scan_part3(const float* __restrict__ A_log_l,
                           const float* __restrict__ D_l) {
    int t = blockIdx.x * blockDim.x + threadIdx.x;
    int c = t >> 14;
    int u = t & (NLANES-1);
    int n = u & 7;
    int d = (u >> 3) & 1023;
    int b = (u >> 13) & 1;

    float A  = -__expf(A_log_l[d*NS + n]);
    float Dv = D_l[d];
    float s  = g_sst[t];
    int l0 = c * CLEN;
    for (int l = l0; l < l0 + CLEN; l++) {
        int m = b*LL + l;
        float dtv = g_dt[(size_t)m*DIM + d];
        float hsv = g_hs[(size_t)m*DIM + d];
        float Bv  = g_sp[(size_t)m*SPW + RR + n];
        float Cv  = g_sp[(size_t)m*SPW + RR + NS + n];
        float dA  = __expf(dtv * A);
        s = dA * s + (dtv * hsv) * Bv;
        float yv = s * Cv;
        yv += __shfl_xor_sync(0xffffffffu, yv, 1);
        yv += __shfl_xor_sync(0xffffffffu, yv, 2);
        yv += __shfl_xor_sync(0xffffffffu, yv, 4);
        if (n == 0) {
            float g  = g_proj[(size_t)m*DI2 + DIM + d];
            float sg = g / (1.f + __expf(-g));
            float yo = (yv + hsv * Dv) * sg;
            bf16 h, lo; split1(yo, h, lo);
            g_y_h[(size_t)m*DIM + d] = h;
            g_y_l[(size_t)m*DIM + d] = lo;
        }
    }
}

// -------------------- launcher --------------------
extern "C" void kernel_launch(void* const* d_in, const int* in_sizes, int n_in,
                              void* d_out, int out_size)
{
    const int*   x         = (const int*)  d_in[0];
    const float* emb       = (const float*)d_in[1];
    const float* in_proj_w = (const float*)d_in[2];
    const float* conv_w    = (const float*)d_in[3];
    const float* conv_b    = (const float*)d_in[4];
    const float* x_proj_w  = (const float*)d_in[5];
    const float* dt_proj_w = (const float*)d_in[6];
    const float* dt_proj_b = (const float*)d_in[7];
    const float* A_log     = (const float*)d_in[8];
    const float* D_ssm     = (const float*)d_in[9];
    const float* out_proj_w= (const float*)d_in[10];
    const float* norm_w    = (const float*)d_in[11];
    const float* norm_f_w  = (const float*)d_in[12];
    const float* head_w    = (const float*)d_in[13];
    const float* head_b    = (const float*)d_in[14];
    float* out = (float*)d_out;

    cudaFuncSetAttribute(gemm_tc, cudaFuncAttributeMaxDynamicSharedMemorySize, GSMEM);

    float *p_h, *p_proj, *p_sp, *p_dt;
    cudaGetSymbolAddress((void**)&p_h,    g_h);
    cudaGetSymbolAddress((void**)&p_proj, g_proj);
    cudaGetSymbolAddress((void**)&p_sp,   g_sp);
    cudaGetSymbolAddress((void**)&p_dt,   g_dt);

    bf16 *p_hn_h,*p_hn_l,*p_hs_h,*p_hs_l,*p_dtr_h,*p_dtr_l,*p_y_h,*p_y_l;
    bf16 *p_wi_h,*p_wi_l,*p_wx_h,*p_wx_l,*p_wd_h,*p_wd_l,*p_wo_h,*p_wo_l,*p_wh_h,*p_wh_l;
    cudaGetSymbolAddress((void**)&p_hn_h, g_hn_h);  cudaGetSymbolAddress((void**)&p_hn_l, g_hn_l);
    cudaGetSymbolAddress((void**)&p_hs_h, g_hs_h);  cudaGetSymbolAddress((void**)&p_hs_l, g_hs_l);
    cudaGetSymbolAddress((void**)&p_dtr_h, g_dtr_h); cudaGetSymbolAddress((void**)&p_dtr_l, g_dtr_l);
    cudaGetSymbolAddress((void**)&p_y_h,  g_y_h);   cudaGetSymbolAddress((void**)&p_y_l,  g_y_l);
    cudaGetSymbolAddress((void**)&p_wi_h, g_wi_h);  cudaGetSymbolAddress((void**)&p_wi_l, g_wi_l);
    cudaGetSymbolAddress((void**)&p_wx_h, g_wx_h);  cudaGetSymbolAddress((void**)&p_wx_l, g_wx_l);
    cudaGetSymbolAddress((void**)&p_wd_h, g_wd_h);  cudaGetSymbolAddress((void**)&p_wd_l, g_wd_l);
    cudaGetSymbolAddress((void**)&p_wo_h, g_wo_h);  cudaGetSymbolAddress((void**)&p_wo_l, g_wo_l);
    cudaGetSymbolAddress((void**)&p_wh_h, g_wh_h);  cudaGetSymbolAddress((void**)&p_wh_l, g_wh_l);

    // ---- split weights ----
    {
        int n4;
        n4 = NLAYERS*DI2*HH/4;
        split_kernel<<<(n4+255)/256, 256>>>((const float4*)in_proj_w, (uint32_t*)p_wi_h, (uint32_t*)p_wi_l, n4);
        n4 = NLAYERS*SPW*DIM/4;
        split_kernel<<<(n4+255)/256, 256>>>((const float4*)x_proj_w, (uint32_t*)p_wx_h, (uint32_t*)p_wx_l, n4);
        n4 = NLAYERS*DIM*RR/4;
        split_kernel<<<(n4+255)/256, 256>>>((const float4*)dt_proj_w, (uint32_t*)p_wd_h, (uint32_t*)p_wd_l, n4);
        n4 = NLAYERS*HH*DIM/4;
        split_kernel<<<(n4+255)/256, 256>>>((const float4*)out_proj_w, (uint32_t*)p_wo_h, (uint32_t*)p_wo_l, n4);
        n4 = VMX*HH/4;
        split_kernel<<<(n4+255)/256, 256>>>((const float4*)head_w, (uint32_t*)p_wh_h, (uint32_t*)p_wh_l, n4);
    }

    embed_kernel<<<MM, HH>>>(x, emb);

    for (int l = 0; l < NLAYERS; l++) {
        rmsnorm_kernel<<<MM, 256>>>(norm_w + l*HH);

        // in_proj: hn[2048,512] x w_in[2048,512]^T -> g_proj (no split-K)
        gemm_tc<<<dim3(DI2/128, MM/128, 1), 256, GSMEM>>>(
            p_hn_h, p_hn_l, p_wi_h + (size_t)l*DI2*HH, p_wi_l + (size_t)l*DI2*HH,
            nullptr, nullptr, p_proj,
            MM, DI2, HH, HH, HH, DI2, 0);

        conv_silu_kernel<<<dim3(MM, DIM/256), 256>>>(
            conv_w + (size_t)l*DIM*KC, conv_b + l*DIM);

        // x_proj: hs[2048,1024] x w_x[48,1024]^T, split-K=8, atomic into zeroed g_sp
        cudaMemsetAsync(p_sp, 0, (size_t)MM*SPW*sizeof(float));
        gemm_tc<<<dim3(1, MM/128, 8), 256, GSMEM>>>(
            p_hs_h, p_hs_l, p_wx_h + (size_t)l*SPW*DIM, p_wx_l + (size_t)l*SPW*DIM,
            nullptr, nullptr, p_sp,
            MM, SPW, DIM/8, DIM, DIM, SPW, 5);

        split_dtr_kernel<<<(MM*8)/256, 256>>>();

        // dt_proj: dtr[2048,32] x w_dt[1024,32]^T +bias softplus -> g_dt
        gemm_tc<<<dim3(DIM/128, MM/128, 1), 256, GSMEM>>>(
            p_dtr_h, p_dtr_l, p_wd_h + (size_t)l*DIM*RR, p_wd_l + (size_t)l*DIM*RR,
            dt_proj_b + l*DIM, nullptr, p_dt,
            MM, DIM, RR, RR, RR, DIM, 1);

        scan_part1<<<(NCHUNK*NLANES)/256, 256>>>(A_log + (size_t)l*DIM*NS);
        scan_part2<<<NLANES/256, 256>>>();
        scan_part3<<<(NCHUNK*NLANES)/256, 256>>>(A_log + (size_t)l*DIM*NS, D_ssm + l*DIM);

        // out_proj + residual: split-K=4, atomic onto g_h (already holds residual)
        gemm_tc<<<dim3(HH/128, MM/128, 4), 256, GSMEM>>>(
            p_y_h, p_y_l, p_wo_h + (size_t)l*HH*DIM, p_wo_l + (size_t)l*HH*DIM,
            nullptr, nullptr, p_h,
            MM, HH, DIM/4, DIM, DIM, HH, 5);
    }

    rmsnorm_kernel<<<MM, 256>>>(norm_f_w);

    // head: split-K=4, atomic onto bias-initialized out
    init_bias_kernel<<<(MM*VMX + 255)/256, 256>>>(out, head_b, MM*VMX);
    gemm_tc<<<dim3((VMX + 127)/128, MM/128, 4), 256, GSMEM>>>(
        p_hn_h, p_hn_l, p_wh_h, p_wh_l,
        nullptr, nullptr, out,
        MM, VMX, HH/4, HH, HH, VMX, 5);
}

// round 7
// speedup vs baseline: 6.1515x; 1.2802x over previous
#include <cuda_runtime.h>
#include <cuda_bf16.h>
#include <math.h>
#include <stdint.h>

#define BB 2
#define LL 1024
#define HH 512
#define DIM 1024
#define DI2 2048
#define NS 8
#define KC 4
#define RR 32
#define NLAYERS 4
#define VMX 300
#define NFEAT 4
#define MM (BB*LL)          /* 2048 rows */
#define SPW 48              /* R + 2N */
#define EPS 1e-5f

#define NCHUNK 16
#define CLEN (LL/NCHUNK)    /* 64 */

typedef __nv_bfloat16 bf16;

// -------------------- scratch (device globals; no allocation) --------------------
__device__ float g_h   [MM*HH];     // residual stream (f32)
__device__ float g_proj[MM*DI2];    // in_proj output (f32; conv + gate)
__device__ float g_hs  [MM*DIM];    // conv+silu (f32; scan)
__device__ float g_sp  [MM*SPW];    // x_proj output (f32)
__device__ float g_dt  [MM*DIM];    // softplus(dt) (f32; scan)

// bf16 hi/lo split operands for GEMMs
__device__ bf16 g_hn_h[MM*HH],  g_hn_l[MM*HH];
__device__ bf16 g_hs_h[MM*DIM], g_hs_l[MM*DIM];
__device__ bf16 g_dtr_h[MM*RR], g_dtr_l[MM*RR];
__device__ bf16 g_y_h[MM*DIM],  g_y_l[MM*DIM];
// split weights
__device__ bf16 g_wi_h[NLAYERS*DI2*HH], g_wi_l[NLAYERS*DI2*HH];
__device__ bf16 g_wx_h[NLAYERS*SPW*DIM], g_wx_l[NLAYERS*SPW*DIM];
__device__ bf16 g_wd_h[NLAYERS*DIM*RR],  g_wd_l[NLAYERS*DIM*RR];
__device__ bf16 g_wo_h[NLAYERS*HH*DIM],  g_wo_l[NLAYERS*HH*DIM];
__device__ bf16 g_wh_h[VMX*HH],          g_wh_l[VMX*HH];

// -------------------- helpers --------------------
__device__ __forceinline__ uint32_t smem_u32(const void* p) {
    return (uint32_t)__cvta_generic_to_shared(p);
}
__device__ __forceinline__ void split1(float v, bf16& h, bf16& l) {
    h = __float2bfloat16_rn(v);
    l = __float2bfloat16_rn(v - __bfloat162float(h));
}
__device__ __forceinline__ void ldsm4(uint32_t* r, uint32_t addr) {
    asm volatile("ldmatrix.sync.aligned.m8n8.x4.shared.b16 {%0,%1,%2,%3}, [%4];"
                 : "=r"(r[0]), "=r"(r[1]), "=r"(r[2]), "=r"(r[3]) : "r"(addr));
}
__device__ __forceinline__ void mma_bf16(float* d, const uint32_t* a, const uint32_t* b) {
    asm volatile(
        "mma.sync.aligned.m16n8k16.row.col.f32.bf16.bf16.f32 "
        "{%0,%1,%2,%3}, {%4,%5,%6,%7}, {%8,%9}, {%0,%1,%2,%3};"
        : "+f"(d[0]), "+f"(d[1]), "+f"(d[2]), "+f"(d[3])
        : "r"(a[0]), "r"(a[1]), "r"(a[2]), "r"(a[3]), "r"(b[0]), "r"(b[1]));
}
__device__ __forceinline__ void cp16(uint32_t dst, const void* src, bool pred) {
    int sz = pred ? 16 : 0;
    asm volatile("cp.async.cg.shared.global [%0], [%1], 16, %2;"
                 :: "r"(dst), "l"(src), "r"(sz) : "memory");
}
#define CP_COMMIT() asm volatile("cp.async.commit_group;" ::: "memory")
#define CP_WAIT(n)  asm volatile("cp.async.wait_group %0;" :: "n"(n) : "memory")

__device__ __forceinline__ void split_f4(float4 v, uint32_t* hp, uint32_t* lp) {
    bf16 h0,l0,h1,l1,h2,l2,h3,l3;
    split1(v.x, h0, l0); split1(v.y, h1, l1);
    split1(v.z, h2, l2); split1(v.w, h3, l3);
    hp[0] = ((uint32_t)__bfloat16_as_ushort(h1) << 16) | __bfloat16_as_ushort(h0);
    hp[1] = ((uint32_t)__bfloat16_as_ushort(h3) << 16) | __bfloat16_as_ushort(h2);
    lp[0] = ((uint32_t)__bfloat16_as_ushort(l1) << 16) | __bfloat16_as_ushort(l0);
    lp[1] = ((uint32_t)__bfloat16_as_ushort(l3) << 16) | __bfloat16_as_ushort(l2);
}

// -------------------- one-shot weight split (all 5 weights) --------------------
#define N_WI (NLAYERS*DI2*HH/4)
#define N_WX (NLAYERS*SPW*DIM/4)
#define N_WD (NLAYERS*DIM*RR/4)
#define N_WO (NLAYERS*HH*DIM/4)
#define N_WH (VMX*HH/4)
#define N_SPLIT (N_WI+N_WX+N_WD+N_WO+N_WH)

__global__ void split_all_kernel(const float4* __restrict__ wi, const float4* __restrict__ wx,
                                 const float4* __restrict__ wd, const float4* __restrict__ wo,
                                 const float4* __restrict__ wh) {
    int i = blockIdx.x * 256 + threadIdx.x;
    if (i >= N_SPLIT) return;
    const float4* src; uint32_t *hi, *lo; int j = i;
    if (j < N_WI)           { src = wi; hi = (uint32_t*)g_wi_h; lo = (uint32_t*)g_wi_l; }
    else if ((j -= N_WI) < N_WX) { src = wx; hi = (uint32_t*)g_wx_h; lo = (uint32_t*)g_wx_l; }
    else if ((j -= N_WX) < N_WD) { src = wd; hi = (uint32_t*)g_wd_h; lo = (uint32_t*)g_wd_l; }
    else if ((j -= N_WD) < N_WO) { src = wo; hi = (uint32_t*)g_wo_h; lo = (uint32_t*)g_wo_l; }
    else                    { j -= N_WO;  src = wh; hi = (uint32_t*)g_wh_h; lo = (uint32_t*)g_wh_l; }
    split_f4(src[j], hi + 2*j, lo + 2*j);
}

// split dt-rank cols of g_sp -> dtr hi/lo (2048 x 32)
__global__ void split_dtr_kernel() {
    int i = blockIdx.x * 256 + threadIdx.x;
    int m  = i >> 3;
    int c4 = (i & 7) * 4;
    float4 v = *reinterpret_cast<const float4*>(&g_sp[(size_t)m*SPW + c4]);
    split_f4(v, reinterpret_cast<uint32_t*>(&g_dtr_h[(size_t)m*RR + c4]),
                reinterpret_cast<uint32_t*>(&g_dtr_l[(size_t)m*RR + c4]));
}

// init out with broadcast bias (head)
__global__ void init_bias_kernel(float* __restrict__ out, const float* __restrict__ b, int n) {
    int i = blockIdx.x * 256 + threadIdx.x;
    if (i < n) out[i] = b[i % VMX];
}

// ==================== GEMM: C (+)= A * B^T, bf16 hi/lo inputs ====================
#define KCH 32
#define SSTB 80
#define TILEB (128*SSTB)
#define STAGEB (4*TILEB)
#define NSTAGE 2
#define GSMEM (NSTAGE*STAGEB)

__device__ __forceinline__ void load_stage(
    uint32_t sbase, const bf16* Ah, const bf16* Al, const bf16* Bh, const bf16* Bl,
    int bm, int bn, int k0, int lda, int ldb, int Ndim, int tid)
{
#pragma unroll
    for (int i = 0; i < 2; i++) {
        int idx = tid + i*256;
        int row = idx >> 2;
        int c4  = idx & 3;
        uint32_t doff = (uint32_t)row * SSTB + (uint32_t)c4 * 16;
        size_t aoff = (size_t)(bm + row) * lda + k0 + c4*8;
        cp16(sbase + doff,           Ah + aoff, true);
        cp16(sbase + TILEB + doff,   Al + aoff, true);
        bool bp = (bn + row) < Ndim;
        int brow = bp ? (bn + row) : 0;
        size_t boff = (size_t)brow * ldb + k0 + c4*8;
        cp16(sbase + 2*TILEB + doff, Bh + boff, bp);
        cp16(sbase + 3*TILEB + doff, Bl + boff, bp);
    }
}

__global__ __launch_bounds__(256, 2)
void gemm_tc(const bf16* __restrict__ Ah, const bf16* __restrict__ Al,
             const bf16* __restrict__ Bh, const bf16* __restrict__ Bl,
             const float* __restrict__ bias,
             float* __restrict__ C,
             int Mdim, int Ndim, int Kdim,
             int lda, int ldb, int ldc, int mode)
{
    extern __shared__ char sm[];
    const int tid  = threadIdx.x;
    const int lane = tid & 31;
    const int wid  = tid >> 5;
    const int warpM = wid & 3;
    const int warpN = wid >> 2;
    const int bm = blockIdx.y * 128;
    const int bn = blockIdx.x * 128;
    const int kOff = blockIdx.z * Kdim;

    float acc[2][8][4];
#pragma unroll
    for (int i = 0; i < 2; i++)
#pragma unroll
        for (int j = 0; j < 8; j++)
#pragma unroll
            for (int q = 0; q < 4; q++) acc[i][j][q] = 0.f;

    const int nch = Kdim / KCH;
    const uint32_t sb0 = smem_u32(sm);

    load_stage(sb0, Ah, Al, Bh, Bl, bm, bn, kOff, lda, ldb, Ndim, tid);
    CP_COMMIT();

    for (int ci = 0; ci < nch; ci++) {
        if (ci + 1 < nch)
            load_stage(sb0 + (uint32_t)((ci+1) & 1)*STAGEB, Ah, Al, Bh, Bl,
                       bm, bn, kOff + (ci+1)*KCH, lda, ldb, Ndim, tid);
        CP_COMMIT();
        CP_WAIT(1);
        __syncthreads();

        const uint32_t uAh = sb0 + (uint32_t)(ci & 1)*STAGEB;
        const uint32_t uAl = uAh + TILEB;
        const uint32_t uBh = uAh + 2*TILEB;
        const uint32_t uBl = uAh + 3*TILEB;

#pragma unroll
        for (int ks = 0; ks < 2; ks++) {
            uint32_t afh[2][4], afl[2][4];
            const int kcA = ks*16 + (lane >> 4) * 8;
            const int rA0 = warpM*32 + (lane & 15);
#pragma unroll
            for (int mi = 0; mi < 2; mi++) {
                uint32_t off = (uint32_t)(rA0 + mi*16) * SSTB + (uint32_t)kcA * 2;
                ldsm4(afh[mi], uAh + off);
                ldsm4(afl[mi], uAl + off);
            }
            const int rB0 = warpN*64 + (lane & 7) + ((lane >> 4) << 3);
            const int kcB = ks*16 + ((lane >> 3) & 1) * 8;
#pragma unroll
            for (int g2 = 0; g2 < 4; g2++) {
                uint32_t off = (uint32_t)(rB0 + g2*16) * SSTB + (uint32_t)kcB * 2;
                uint32_t th[4], tl[4];
                ldsm4(th, uBh + off);
                ldsm4(tl, uBl + off);
#pragma unroll
                for (int mi = 0; mi < 2; mi++) {
                    mma_bf16(acc[mi][2*g2],   afh[mi], th);
                    mma_bf16(acc[mi][2*g2],   afh[mi], tl);
                    mma_bf16(acc[mi][2*g2],   afl[mi], th);
                    mma_bf16(acc[mi][2*g2+1], afh[mi], th+2);
                    mma_bf16(acc[mi][2*g2+1], afh[mi], tl+2);
                    mma_bf16(acc[mi][2*g2+1], afl[mi], th+2);
                }
            }
        }
        __syncthreads();
    }

    // epilogue
#pragma unroll
    for (int mi = 0; mi < 2; mi++) {
        const int row0 = bm + warpM*32 + mi*16 + (lane >> 2);
#pragma unroll
        for (int g = 0; g < 8; g++) {
            const int col = bn + warpN*64 + g*8 + (lane & 3)*2;
            if (col >= Ndim) continue;
#pragma unroll
            for (int h = 0; h < 2; h++) {
                const int r = row0 + h*8;
                float v0 = acc[mi][g][2*h+0];
                float v1 = acc[mi][g][2*h+1];
                if (mode == 5) {
                    atomicAdd(C + (size_t)r*ldc + col,     v0);
                    if (col + 1 < Ndim) atomicAdd(C + (size_t)r*ldc + col + 1, v1);
                    continue;
                }
                if (mode == 1) {
                    v0 += bias[col]; v1 += bias[col+1];
                    v0 = (v0 > 20.f) ? v0 : log1pf(expf(v0));
                    v1 = (v1 > 20.f) ? v1 : log1pf(expf(v1));
                }
                *reinterpret_cast<float2*>(C + (size_t)r*ldc + col) = make_float2(v0, v1);
            }
        }
    }
}

// -------------------- fused embed + rmsnorm (layer 0) --------------------
__global__ void embed_rmsnorm_kernel(const int* __restrict__ x, const float* __restrict__ emb,
                                     const float* __restrict__ w) {
    int m = blockIdx.x;
    int t = threadIdx.x;     // 512 threads
    float s = 0.f;
#pragma unroll
    for (int i = 0; i < NFEAT; i++) {
        int v = x[m*NFEAT + i];
        s += emb[((size_t)i*VMX + v)*HH + t];
    }
    g_h[(size_t)m*HH + t] = s;

    // reduce s*s over 512 threads
    float q = s * s;
#pragma unroll
    for (int o = 16; o > 0; o >>= 1) q += __shfl_xor_sync(0xffffffffu, q, o);
    __shared__ float red[16];
    if ((t & 31) == 0) red[t >> 5] = q;
    __syncthreads();
    if (t < 16) {
        float v = red[t];
#pragma unroll
        for (int o = 8; o > 0; o >>= 1) v += __shfl_xor_sync(0xffffu, v, o);
        if (t == 0) red[0] = v;
    }
    __syncthreads();
    float r = rsqrtf(red[0] * (1.f/HH) + EPS);
    float v = s * r * w[t];
    bf16 h, l; split1(v, h, l);
    g_hn_h[(size_t)m*HH + t] = h;
    g_hn_l[(size_t)m*HH + t] = l;
    if (t < SPW) g_sp[(size_t)m*SPW + t] = 0.f;   // pre-zero for x_proj atomics
}

// -------------------- rmsnorm (layers 1..3, final) --------------------
__global__ void rmsnorm_kernel(const float* __restrict__ w) {
    int m = blockIdx.x;
    int tid = threadIdx.x;     // 256
    const float* row = g_h + (size_t)m*HH;
    float s = 0.f;
    for (int i = tid; i < HH; i += 256) { float v = row[i]; s += v*v; }
    __shared__ float red[256];
    red[tid] = s; __syncthreads();
    for (int st = 128; st > 0; st >>= 1) {
        if (tid < st) red[tid] += red[tid + st];
        __syncthreads();
    }
    float r = rsqrtf(red[0] * (1.f/HH) + EPS);
    for (int i = tid; i < HH; i += 256) {
        float v = row[i] * r * w[i];
        bf16 h, l; split1(v, h, l);
        g_hn_h[(size_t)m*HH + i] = h;
        g_hn_l[(size_t)m*HH + i] = l;
    }
    if (tid < SPW) g_sp[(size_t)m*SPW + tid] = 0.f;   // pre-zero for x_proj atomics
}

// -------------------- causal depthwise conv (K=4) + silu --------------------
__global__ void conv_silu_kernel(const float* __restrict__ cw, const float* __restrict__ cb) {
    int m = blockIdx.x;
    int d = blockIdx.y * 256 + threadIdx.x;
    int b = m / LL, l = m % LL;
    float c = cb[d];
#pragma unroll
    for (int k = 0; k < KC; k++) {
        int li = l - (KC - 1) + k;
        if (li >= 0)
            c += g_proj[((size_t)(b*LL + li))*DI2 + d] * cw[d*KC + k];
    }
    float s = c / (1.f + __expf(-c));
    g_hs[(size_t)m*DIM + d] = s;
    bf16 h, lo; split1(s, h, lo);
    g_hs_h[(size_t)m*DIM + d] = h;
    g_hs_l[(size_t)m*DIM + d] = lo;
}

// -------------------- fused selective scan (single kernel) --------------------
// CTA: (b, 2 d's). 256 threads: n = tid&7, dd = (tid>>3)&1, chunk c = tid>>4.
__global__ __launch_bounds__(256)
void scan_fused(const float* __restrict__ A_log_l, const float* __restrict__ D_l) {
    const int tid = threadIdx.x;
    const int n  = tid & 7;
    const int dd = (tid >> 3) & 1;
    const int c  = tid >> 4;               // 0..15
    const int blk = blockIdx.x;            // 0..1023
    const int b = blk >> 9;
    const int d = (blk & 511) * 2 + dd;
    const int g = dd * 8 + n;              // 0..15

    const float A  = -__expf(A_log_l[d*NS + n]);
    const float Dv = D_l[d];

    __shared__ float s_loc[NCHUNK][16];
    __shared__ float s_prod[NCHUNK][16];
    __shared__ float s_sst[NCHUNK][17];

    const int l0 = c * CLEN;

    // phase 1: local scan, s0 = 0
    {
        float s = 0.f, P = 1.f;
        for (int l = l0; l < l0 + CLEN; l++) {
            int m = b*LL + l;
            float dtv = g_dt[(size_t)m*DIM + d];
            float hsv = g_hs[(size_t)m*DIM + d];
            float Bv  = g_sp[(size_t)m*SPW + RR + n];
            float dA  = __expf(dtv * A);
            s = dA * s + (dtv * hsv) * Bv;
            P *= dA;
        }
        s_loc[c][g] = s;
        s_prod[c][g] = P;
    }
    __syncthreads();

    // phase 2: serial combine across chunks (16 threads, one per lane-group)
    if (tid < 16) {
        float s = 0.f;
#pragma unroll
        for (int cc = 0; cc < NCHUNK; cc++) {
            s_sst[cc][tid] = s;
            s = s_loc[cc][tid] + s_prod[cc][tid] * s;
        }
    }
    __syncthreads();

    // phase 3: rescan with correct initial state, emit gated y
    {
        float s = s_sst[c][g];
        for (int l = l0; l < l0 + CLEN; l++) {
            int m = b*LL + l;
            float dtv = g_dt[(size_t)m*DIM + d];
            float hsv = g_hs[(size_t)m*DIM + d];
            float Bv  = g_sp[(size_t)m*SPW + RR + n];
            float Cv  = g_sp[(size_t)m*SPW + RR + NS + n];
            float dA  = __expf(dtv * A);
            s = dA * s + (dtv * hsv) * Bv;
            float yv = s * Cv;
            yv += __shfl_xor_sync(0xffffffffu, yv, 1);
            yv += __shfl_xor_sync(0xffffffffu, yv, 2);
            yv += __shfl_xor_sync(0xffffffffu, yv, 4);
            if (n == 0) {
                float gt  = g_proj[(size_t)m*DI2 + DIM + d];
                float sg = gt / (1.f + __expf(-gt));
                float yo = (yv + hsv * Dv) * sg;
                bf16 h, lo; split1(yo, h, lo);
                g_y_h[(size_t)m*DIM + d] = h;
                g_y_l[(size_t)m*DIM + d] = lo;
            }
        }
    }
}

// -------------------- launcher --------------------
extern "C" void kernel_launch(void* const* d_in, const int* in_sizes, int n_in,
                              void* d_out, int out_size)
{
    const int*   x         = (const int*)  d_in[0];
    const float* emb       = (const float*)d_in[1];
    const float* in_proj_w = (const float*)d_in[2];
    const float* conv_w    = (const float*)d_in[3];
    const float* conv_b    = (const float*)d_in[4];
    const float* x_proj_w  = (const float*)d_in[5];
    const float* dt_proj_w = (const float*)d_in[6];
    const float* dt_proj_b = (const float*)d_in[7];
    const float* A_log     = (const float*)d_in[8];
    const float* D_ssm     = (const float*)d_in[9];
    const float* out_proj_w= (const float*)d_in[10];
    const float* norm_w    = (const float*)d_in[11];
    const float* norm_f_w  = (const float*)d_in[12];
    const float* head_w    = (const float*)d_in[13];
    const float* head_b    = (const float*)d_in[14];
    float* out = (float*)d_out;

    cudaFuncSetAttribute(gemm_tc, cudaFuncAttributeMaxDynamicSharedMemorySize, GSMEM);

    float *p_h, *p_proj, *p_sp, *p_dt;
    cudaGetSymbolAddress((void**)&p_h,    g_h);
    cudaGetSymbolAddress((void**)&p_proj, g_proj);
    cudaGetSymbolAddress((void**)&p_sp,   g_sp);
    cudaGetSymbolAddress((void**)&p_dt,   g_dt);

    bf16 *p_hn_h,*p_hn_l,*p_hs_h,*p_hs_l,*p_dtr_h,*p_dtr_l,*p_y_h,*p_y_l;
    bf16 *p_wi_h,*p_wi_l,*p_wx_h,*p_wx_l,*p_wd_h,*p_wd_l,*p_wo_h,*p_wo_l,*p_wh_h,*p_wh_l;
    cudaGetSymbolAddress((void**)&p_hn_h, g_hn_h);  cudaGetSymbolAddress((void**)&p_hn_l, g_hn_l);
    cudaGetSymbolAddress((void**)&p_hs_h, g_hs_h);  cudaGetSymbolAddress((void**)&p_hs_l, g_hs_l);
    cudaGetSymbolAddress((void**)&p_dtr_h, g_dtr_h); cudaGetSymbolAddress((void**)&p_dtr_l, g_dtr_l);
    cudaGetSymbolAddress((void**)&p_y_h,  g_y_h);   cudaGetSymbolAddress((void**)&p_y_l,  g_y_l);
    cudaGetSymbolAddress((void**)&p_wi_h, g_wi_h);  cudaGetSymbolAddress((void**)&p_wi_l, g_wi_l);
    cudaGetSymbolAddress((void**)&p_wx_h, g_wx_h);  cudaGetSymbolAddress((void**)&p_wx_l, g_wx_l);
    cudaGetSymbolAddress((void**)&p_wd_h, g_wd_h);  cudaGetSymbolAddress((void**)&p_wd_l, g_wd_l);
    cudaGetSymbolAddress((void**)&p_wo_h, g_wo_h);  cudaGetSymbolAddress((void**)&p_wo_l, g_wo_l);
    cudaGetSymbolAddress((void**)&p_wh_h, g_wh_h);  cudaGetSymbolAddress((void**)&p_wh_l, g_wh_l);

    // one-shot weight split
    split_all_kernel<<<(N_SPLIT + 255)/256, 256>>>(
        (const float4*)in_proj_w, (const float4*)x_proj_w, (const float4*)dt_proj_w,
        (const float4*)out_proj_w, (const float4*)head_w);

    // fused embed + rmsnorm (layer 0), also zeroes g_sp
    embed_rmsnorm_kernel<<<MM, HH>>>(x, emb, norm_w);

    for (int l = 0; l < NLAYERS; l++) {
        if (l > 0)
            rmsnorm_kernel<<<MM, 256>>>(norm_w + l*HH);

        // in_proj: hn[2048,512] x w_in[2048,512]^T -> g_proj
        gemm_tc<<<dim3(DI2/128, MM/128, 1), 256, GSMEM>>>(
            p_hn_h, p_hn_l, p_wi_h + (size_t)l*DI2*HH, p_wi_l + (size_t)l*DI2*HH,
            nullptr, p_proj,
            MM, DI2, HH, HH, HH, DI2, 0);

        conv_silu_kernel<<<dim3(MM, DIM/256), 256>>>(
            conv_w + (size_t)l*DIM*KC, conv_b + l*DIM);

        // x_proj: split-K=8, atomic into pre-zeroed g_sp
        gemm_tc<<<dim3(1, MM/128, 8), 256, GSMEM>>>(
            p_hs_h, p_hs_l, p_wx_h + (size_t)l*SPW*DIM, p_wx_l + (size_t)l*SPW*DIM,
            nullptr, p_sp,
            MM, SPW, DIM/8, DIM, DIM, SPW, 5);

        split_dtr_kernel<<<(MM*8)/256, 256>>>();

        // dt_proj: +bias softplus -> g_dt
        gemm_tc<<<dim3(DIM/128, MM/128, 1), 256, GSMEM>>>(
            p_dtr_h, p_dtr_l, p_wd_h + (size_t)l*DIM*RR, p_wd_l + (size_t)l*DIM*RR,
            dt_proj_b + l*DIM, p_dt,
            MM, DIM, RR, RR, RR, DIM, 1);

        // fused scan (one kernel)
        scan_fused<<<BB*DIM/2, 256>>>(A_log + (size_t)l*DIM*NS, D_ssm + l*DIM);

        // out_proj + residual: split-K=4, atomic onto g_h
        gemm_tc<<<dim3(HH/128, MM/128, 4), 256, GSMEM>>>(
            p_y_h, p_y_l, p_wo_h + (size_t)l*HH*DIM, p_wo_l + (size_t)l*HH*DIM,
            nullptr, p_h,
            MM, HH, DIM/4, DIM, DIM, HH, 5);
    }

    rmsnorm_kernel<<<MM, 256>>>(norm_f_w);

    // head: split-K=4, atomic onto bias-initialized out
    init_bias_kernel<<<(MM*VMX + 255)/256, 256>>>(out, head_b, MM*VMX);
    gemm_tc<<<dim3((VMX + 127)/128, MM/128, 4), 256, GSMEM>>>(
        p_hn_h, p_hn_l, p_wh_h, p_wh_l,
        nullptr, out,
        MM, VMX, HH/4, HH, HH, VMX, 5);
}